// round 2
// baseline (speedup 1.0000x reference)
#include <cuda_runtime.h>
#include <cuda_bf16.h>
#include <math.h>

// ---------------- problem constants ----------------
#define S      2048
#define DM     1024
#define H      16
#define DH     64
#define DMLP   4096
#define NV     50257
#define L      2
#define QKVN   (3*DM)      // 3072

// ---------------- static scratch (no allocations allowed) ----------------
__device__ float g_resid[S*DM];       // 8 MB
__device__ float g_x[S*DM];           // 8 MB  (LN output)
__device__ float g_qkv[S*QKVN];       // 24 MB
__device__ float g_z[S*DM];           // 8 MB
__device__ float g_post[S*DMLP];      // 32 MB
__device__ float g_wqkv[DM*QKVN];     // 12 MB packed per-layer QKV weights
__device__ float g_bqkv[QKVN];

// ---------------- embed ----------------
__global__ void embed_kernel(const int* __restrict__ tok,
                             const float* __restrict__ WE,
                             const float* __restrict__ Wpos,
                             float* __restrict__ resid) {
    int i = blockIdx.x * 256 + threadIdx.x;
    if (i >= S*DM) return;
    int s = i >> 10;
    int d = i & (DM-1);
    resid[i] = WE[(size_t)tok[s]*DM + d] + Wpos[i];
}

// ---------------- layernorm (block per row) ----------------
__global__ void ln_kernel(const float* __restrict__ x,
                          const float* __restrict__ w,
                          const float* __restrict__ b,
                          float* __restrict__ y) {
    __shared__ float rs[256], rs2[256];
    int r = blockIdx.x, tid = threadIdx.x;
    const float* xr = x + (size_t)r*DM;
    float s = 0.f, s2 = 0.f;
    #pragma unroll
    for (int i = tid; i < DM; i += 256) { float v = xr[i]; s += v; s2 += v*v; }
    rs[tid] = s; rs2[tid] = s2; __syncthreads();
    for (int o = 128; o > 0; o >>= 1) {
        if (tid < o) { rs[tid] += rs[tid+o]; rs2[tid] += rs2[tid+o]; }
        __syncthreads();
    }
    float mu  = rs[0] * (1.f/DM);
    float var = rs2[0] * (1.f/DM) - mu*mu;
    float inv = rsqrtf(var + 1e-5f);
    float* yr = y + (size_t)r*DM;
    for (int i = tid; i < DM; i += 256)
        yr[i] = (xr[i] - mu) * inv * w[i] + b[i];
}

// ---------------- pack QKV weights for layer l into [DM, 3*DM] ----------------
__global__ void pack_qkv_kernel(const float* __restrict__ WQ,
                                const float* __restrict__ WK,
                                const float* __restrict__ WV,
                                const float* __restrict__ bQ,
                                const float* __restrict__ bK,
                                const float* __restrict__ bV) {
    int idx = blockIdx.x * 256 + threadIdx.x;
    if (idx >= DM*DM) return;
    int d = idx >> 10;          // DM row
    int c = idx & (DM-1);       // h*DH+e column
    int h = c >> 6, e = c & (DH-1);
    size_t src = ((size_t)h*DM + d)*DH + e;   // W[h][d][e]
    g_wqkv[(size_t)d*QKVN + c]        = WQ[src];
    g_wqkv[(size_t)d*QKVN + DM + c]   = WK[src];
    g_wqkv[(size_t)d*QKVN + 2*DM + c] = WV[src];
    if (idx < DM) {
        g_bqkv[idx]        = bQ[idx];
        g_bqkv[DM + idx]   = bK[idx];
        g_bqkv[2*DM + idx] = bV[idx];
    }
}

// ---------------- tiled SGEMM: C = act(A@B + bias) (+ R) ----------------
// A: [M,K] row-major, B: [K,N] row-major. M must be multiple of 128.
// ACT: 0 = none, 1 = exact GELU (applied before residual add, per reference)
template <int ACT>
__global__ void sgemm_kernel(const float* __restrict__ A,
                             const float* __restrict__ B,
                             const float* __restrict__ bias,
                             const float* __restrict__ R,
                             float* __restrict__ C,
                             int M, int N, int K) {
    const int BM = 128, BN = 64, BK = 16;
    __shared__ float As[BK][BM+4];
    __shared__ float Bs[BK][BN+4];
    int tid = threadIdx.x;            // 256 threads, 16x16 layout
    int tx = tid & 15, ty = tid >> 4;
    int row0 = blockIdx.y * BM, col0 = blockIdx.x * BN;

    float acc[8][4];
    #pragma unroll
    for (int i = 0; i < 8; i++)
        #pragma unroll
        for (int j = 0; j < 4; j++) acc[i][j] = 0.f;

    for (int k0 = 0; k0 < K; k0 += BK) {
        #pragma unroll
        for (int t = 0; t < 8; t++) {             // A tile: 128x16
            int i = tid + t*256;
            int m = i >> 4, kk = i & 15;
            As[kk][m] = A[(size_t)(row0+m)*K + k0 + kk];
        }
        #pragma unroll
        for (int t = 0; t < 4; t++) {             // B tile: 16x64
            int i = tid + t*256;
            int kk = i >> 6, n = i & 63;
            int col = col0 + n;
            Bs[kk][n] = (col < N) ? B[(size_t)(k0+kk)*N + col] : 0.f;
        }
        __syncthreads();
        #pragma unroll
        for (int kk = 0; kk < BK; kk++) {
            float a[8], bb[4];
            #pragma unroll
            for (int i = 0; i < 8; i++) a[i] = As[kk][ty*8+i];
            #pragma unroll
            for (int j = 0; j < 4; j++) bb[j] = Bs[kk][tx*4+j];
            #pragma unroll
            for (int i = 0; i < 8; i++)
                #pragma unroll
                for (int j = 0; j < 4; j++)
                    acc[i][j] = fmaf(a[i], bb[j], acc[i][j]);
        }
        __syncthreads();
    }

    #pragma unroll
    for (int i = 0; i < 8; i++) {
        int row = row0 + ty*8 + i;
        #pragma unroll
        for (int j = 0; j < 4; j++) {
            int col = col0 + tx*4 + j;
            if (col >= N) continue;
            float v = acc[i][j];
            if (bias) v += bias[col];
            if (ACT == 1) v = 0.5f * v * (1.f + erff(v * 0.70710678118654752f));
            if (R) v += R[(size_t)row*N + col];
            C[(size_t)row*N + col] = v;
        }
    }
}

// ---------------- fused causal attention: one block per (query, head) -----
__global__ void attn_kernel(const float* __restrict__ qkv,
                            float* __restrict__ z) {
    int s = blockIdx.x;
    int h = blockIdx.y;
    int tid = threadIdx.x;       // 256 threads
    __shared__ float qs[DH];
    __shared__ float sc[S];
    __shared__ float red[256];
    __shared__ float zacc[4][DH];

    if (tid < DH) qs[tid] = qkv[(size_t)s*QKVN + h*DH + tid];
    __syncthreads();

    int nk = s + 1;
    const float scale = 0.125f;  // 1/sqrt(64)

    // scores (causal region only; masked entries underflow to exactly 0 prob)
    for (int t = tid; t < nk; t += 256) {
        const float* kp = qkv + (size_t)t*QKVN + DM + h*DH;
        float d = 0.f;
        #pragma unroll
        for (int e = 0; e < DH; e++) d = fmaf(qs[e], kp[e], d);
        sc[t] = d * scale;
    }
    __syncthreads();

    // max
    float m = -1e30f;
    for (int t = tid; t < nk; t += 256) m = fmaxf(m, sc[t]);
    red[tid] = m; __syncthreads();
    for (int o = 128; o > 0; o >>= 1) {
        if (tid < o) red[tid] = fmaxf(red[tid], red[tid+o]);
        __syncthreads();
    }
    m = red[0];
    __syncthreads();

    // exp + sum
    float lsum = 0.f;
    for (int t = tid; t < nk; t += 256) {
        float p = expf(sc[t] - m);
        sc[t] = p;
        lsum += p;
    }
    red[tid] = lsum; __syncthreads();
    for (int o = 128; o > 0; o >>= 1) {
        if (tid < o) red[tid] += red[tid+o];
        __syncthreads();
    }
    float inv = 1.f / red[0];
    __syncthreads();

    // z[e] = sum_t p[t] * v[t][e]; 4 groups of 64 threads over t
    int e = tid & 63, g = tid >> 6;
    float acc = 0.f;
    for (int t = g; t < nk; t += 4)
        acc = fmaf(sc[t], qkv[(size_t)t*QKVN + 2*DM + h*DH + e], acc);
    zacc[g][e] = acc;
    __syncthreads();
    if (tid < DH)
        z[(size_t)s*DM + h*DH + tid] =
            (zacc[0][tid] + zacc[1][tid] + zacc[2][tid] + zacc[3][tid]) * inv;
}

// ---------------- plain copy ----------------
__global__ void copy_kernel(const float* __restrict__ src, float* __restrict__ dst, int n) {
    int i = blockIdx.x * 256 + threadIdx.x;
    if (i < n) dst[i] = src[i];
}

// ---------------- launcher ----------------
extern "C" void kernel_launch(void* const* d_in, const int* in_sizes, int n_in,
                              void* d_out, int out_size) {
    const int*   tokens = (const int*)  d_in[0];
    const float* W_E    = (const float*)d_in[1];
    const float* W_pos  = (const float*)d_in[2];
    const float* ln1_w  = (const float*)d_in[3];
    const float* ln1_b  = (const float*)d_in[4];
    const float* W_Q    = (const float*)d_in[5];
    const float* b_Q    = (const float*)d_in[6];
    const float* W_K    = (const float*)d_in[7];
    const float* b_K    = (const float*)d_in[8];
    const float* W_V    = (const float*)d_in[9];
    const float* b_V    = (const float*)d_in[10];
    const float* W_O    = (const float*)d_in[11];
    const float* b_O    = (const float*)d_in[12];
    const float* ln2_w  = (const float*)d_in[13];
    const float* ln2_b  = (const float*)d_in[14];
    const float* W_in   = (const float*)d_in[15];
    const float* b_in   = (const float*)d_in[16];
    const float* W_out  = (const float*)d_in[17];
    const float* b_out  = (const float*)d_in[18];
    const float* lnf_w  = (const float*)d_in[19];
    const float* lnf_b  = (const float*)d_in[20];
    const float* W_U    = (const float*)d_in[21];
    const float* b_U    = (const float*)d_in[22];

    float *p_resid, *p_x, *p_qkv, *p_z, *p_post, *p_wqkv, *p_bqkv;
    cudaGetSymbolAddress((void**)&p_resid, g_resid);
    cudaGetSymbolAddress((void**)&p_x,     g_x);
    cudaGetSymbolAddress((void**)&p_qkv,   g_qkv);
    cudaGetSymbolAddress((void**)&p_z,     g_z);
    cudaGetSymbolAddress((void**)&p_post,  g_post);
    cudaGetSymbolAddress((void**)&p_wqkv,  g_wqkv);
    cudaGetSymbolAddress((void**)&p_bqkv,  g_bqkv);

    float* out = (float*)d_out;

    // embed
    embed_kernel<<<(S*DM + 255)/256, 256>>>(tokens, W_E, W_pos, p_resid);

    for (int l = 0; l < L; l++) {
        const float* wq = W_Q + (size_t)l*H*DM*DH;
        const float* wk = W_K + (size_t)l*H*DM*DH;
        const float* wv = W_V + (size_t)l*H*DM*DH;
        const float* wo = W_O + (size_t)l*H*DH*DM;   // [(h*DH+e), d] contiguous
        const float* bq = b_Q + (size_t)l*H*DH;
        const float* bk = b_K + (size_t)l*H*DH;
        const float* bv = b_V + (size_t)l*H*DH;
        const float* bo = b_O + (size_t)l*DM;
        const float* l1w = ln1_w + (size_t)l*DM, *l1b = ln1_b + (size_t)l*DM;
        const float* l2w = ln2_w + (size_t)l*DM, *l2b = ln2_b + (size_t)l*DM;
        const float* wi = W_in  + (size_t)l*DM*DMLP;
        const float* bi = b_in  + (size_t)l*DMLP;
        const float* wu2= W_out + (size_t)l*DMLP*DM;
        const float* bo2= b_out + (size_t)l*DM;

        pack_qkv_kernel<<<(DM*DM + 255)/256, 256>>>(wq, wk, wv, bq, bk, bv);

        ln_kernel<<<S, 256>>>(p_resid, l1w, l1b, p_x);

        // qkv = x @ wqkv + bqkv   [2048, 3072]
        sgemm_kernel<0><<<dim3(QKVN/64, S/128), 256>>>(
            p_x, p_wqkv, p_bqkv, nullptr, p_qkv, S, QKVN, DM);

        attn_kernel<<<dim3(S, H), 256>>>(p_qkv, p_z);

        // resid = z @ W_O + b_O + resid   (in-place residual add)
        sgemm_kernel<0><<<dim3(DM/64, S/128), 256>>>(
            p_z, wo, bo, p_resid, p_resid, S, DM, DM);

        ln_kernel<<<S, 256>>>(p_resid, l2w, l2b, p_x);

        // post = gelu(x @ W_in + b_in)   [2048, 4096]
        sgemm_kernel<1><<<dim3(DMLP/64, S/128), 256>>>(
            p_x, wi, bi, nullptr, p_post, S, DMLP, DM);

        // resid = post @ W_out + b_out + resid
        sgemm_kernel<0><<<dim3(DM/64, S/128), 256>>>(
            p_post, wu2, bo2, p_resid, p_resid, S, DM, DMLP);
    }

    // final LN + unembed -> logits directly into d_out
    ln_kernel<<<S, 256>>>(p_resid, lnf_w, lnf_b, p_x);
    sgemm_kernel<0><<<dim3((NV + 63)/64, S/128), 256>>>(
        p_x, W_U, b_U, nullptr, out, S, NV, DM);

    // extra outputs (residual, post) if the harness expects the full tuple
    const long long LOG_N  = (long long)S * NV;
    const long long RES_N  = (long long)S * DM;
    const long long POST_N = (long long)S * DMLP;
    long long osz = (long long)out_size;
    if (osz >= LOG_N + RES_N)
        copy_kernel<<<(int)((RES_N + 255)/256), 256>>>(p_resid, out + LOG_N, (int)RES_N);
    if (osz >= LOG_N + RES_N + POST_N)
        copy_kernel<<<(int)((POST_N + 255)/256), 256>>>(p_post, out + LOG_N + RES_N, (int)POST_N);
}

// round 3
// speedup vs baseline: 1.0045x; 1.0045x over previous
#include <cuda_runtime.h>
#include <cuda_bf16.h>
#include <math.h>
#include <stdint.h>

// ---------------- problem constants ----------------
#define S      2048
#define DM     1024
#define H      16
#define DH     64
#define DMLP   4096
#define NV     50257
#define L      2
#define QKVN   (3*DM)      // 3072

// ---------------- static scratch (no allocations allowed) ----------------
__device__ float g_resid[S*DM];       // 8 MB
__device__ float g_x[S*DM];           // 8 MB  (LN output)
__device__ float g_qkv[S*QKVN];       // 24 MB
__device__ float g_z[S*DM];           // 8 MB
__device__ float g_post[S*DMLP];      // 32 MB
__device__ float g_wqkv[DM*QKVN];     // 12 MB packed per-layer QKV weights
__device__ float g_bqkv[QKVN];

// ---------------- embed ----------------
__global__ void embed_kernel(const int* __restrict__ tok,
                             const float* __restrict__ WE,
                             const float* __restrict__ Wpos,
                             float* __restrict__ resid) {
    int i = blockIdx.x * 256 + threadIdx.x;
    if (i >= S*DM) return;
    int s = i >> 10;
    int d = i & (DM-1);
    resid[i] = WE[(size_t)tok[s]*DM + d] + Wpos[i];
}

// ---------------- layernorm (block per row) ----------------
__global__ void ln_kernel(const float* __restrict__ x,
                          const float* __restrict__ w,
                          const float* __restrict__ b,
                          float* __restrict__ y) {
    __shared__ float rs[256], rs2[256];
    int r = blockIdx.x, tid = threadIdx.x;
    const float* xr = x + (size_t)r*DM;
    float s = 0.f, s2 = 0.f;
    #pragma unroll
    for (int i = tid; i < DM; i += 256) { float v = xr[i]; s += v; s2 += v*v; }
    rs[tid] = s; rs2[tid] = s2; __syncthreads();
    for (int o = 128; o > 0; o >>= 1) {
        if (tid < o) { rs[tid] += rs[tid+o]; rs2[tid] += rs2[tid+o]; }
        __syncthreads();
    }
    float mu  = rs[0] * (1.f/DM);
    float var = rs2[0] * (1.f/DM) - mu*mu;
    float inv = rsqrtf(var + 1e-5f);
    float* yr = y + (size_t)r*DM;
    for (int i = tid; i < DM; i += 256)
        yr[i] = (xr[i] - mu) * inv * w[i] + b[i];
}

// ---------------- pack QKV weights for layer l into [DM, 3*DM] ----------------
__global__ void pack_qkv_kernel(const float* __restrict__ WQ,
                                const float* __restrict__ WK,
                                const float* __restrict__ WV,
                                const float* __restrict__ bQ,
                                const float* __restrict__ bK,
                                const float* __restrict__ bV) {
    int idx = blockIdx.x * 256 + threadIdx.x;
    if (idx >= DM*DM) return;
    int d = idx >> 10;          // DM row
    int c = idx & (DM-1);       // h*DH+e column
    int h = c >> 6, e = c & (DH-1);
    size_t src = ((size_t)h*DM + d)*DH + e;   // W[h][d][e]
    g_wqkv[(size_t)d*QKVN + c]        = WQ[src];
    g_wqkv[(size_t)d*QKVN + DM + c]   = WK[src];
    g_wqkv[(size_t)d*QKVN + 2*DM + c] = WV[src];
    if (idx < DM) {
        g_bqkv[idx]        = bQ[idx];
        g_bqkv[DM + idx]   = bK[idx];
        g_bqkv[2*DM + idx] = bV[idx];
    }
}

// ---------------- tf32 helpers ----------------
__device__ __forceinline__ uint32_t f2tf32(float x) {
    uint32_t r;
    asm("cvt.rna.tf32.f32 %0, %1;" : "=r"(r) : "f"(x));
    return r;
}

__device__ __forceinline__ void mma_tf32(float c[4],
                                         const uint32_t a[4],
                                         const uint32_t b[2]) {
    asm volatile(
        "mma.sync.aligned.m16n8k8.row.col.f32.tf32.tf32.f32 "
        "{%0,%1,%2,%3}, {%4,%5,%6,%7}, {%8,%9}, {%0,%1,%2,%3};\n"
        : "+f"(c[0]), "+f"(c[1]), "+f"(c[2]), "+f"(c[3])
        : "r"(a[0]), "r"(a[1]), "r"(a[2]), "r"(a[3]),
          "r"(b[0]), "r"(b[1]));
}

// ---------------- tensor-core GEMM with 3xTF32 split ------------------
// C = act(A@B + bias) (+ R).  A:[M,K] rm, B:[K,N] rm.  M%128==0, K%16==0.
// ACT: 0 none, 1 exact GELU (before residual add).
#define BM 128
#define BN 64
#define BK 16
#define ASTR (BM+4)   // 132 -> frag bank = (4k+m)%32, conflict-free
#define BSTR (BN+4)   // 68  -> frag bank = (4k+n)%32, conflict-free

template <int ACT>
__global__ __launch_bounds__(256, 2)
void mma_gemm_kernel(const float* __restrict__ A,
                     const float* __restrict__ B,
                     const float* __restrict__ bias,
                     const float* __restrict__ R,
                     float* __restrict__ C,
                     int M, int N, int K) {
    __shared__ float As[2][BK][ASTR];   // [hi/lo][k][m]
    __shared__ float Bs[2][BK][BSTR];   // [hi/lo][k][n]

    const int tid  = threadIdx.x;
    const int lane = tid & 31;
    const int wid  = tid >> 5;          // 8 warps
    const int g    = lane >> 2;         // 0..7
    const int t4   = lane & 3;          // 0..3
    const int wm   = wid >> 1;          // 0..3 -> 32-row slab
    const int wn   = wid & 1;           // 0..1 -> 32-col slab
    const int row0 = blockIdx.y * BM;
    const int col0 = blockIdx.x * BN;
    const bool n4  = (N & 3) == 0;

    float acc[2][4][4];
    #pragma unroll
    for (int mt = 0; mt < 2; mt++)
        #pragma unroll
        for (int nt = 0; nt < 4; nt++)
            #pragma unroll
            for (int i = 0; i < 4; i++) acc[mt][nt][i] = 0.f;

    for (int k0 = 0; k0 < K; k0 += BK) {
        // ---- stage A tile: 128x16 = 512 float4, 2 per thread ----
        #pragma unroll
        for (int t = 0; t < 2; t++) {
            int idx = tid + t*256;
            int r   = idx >> 2;         // 0..127
            int c4  = idx & 3;          // 0..3
            float4 v = *reinterpret_cast<const float4*>(
                &A[(size_t)(row0 + r)*K + k0 + c4*4]);
            float xs[4] = {v.x, v.y, v.z, v.w};
            #pragma unroll
            for (int e = 0; e < 4; e++) {
                float hi = __uint_as_float(f2tf32(xs[e]));
                As[0][c4*4 + e][r] = hi;
                As[1][c4*4 + e][r] = xs[e] - hi;
            }
        }
        // ---- stage B tile: 16x64 = 256 float4, 1 per thread ----
        {
            int r  = tid >> 4;          // k row 0..15
            int c4 = tid & 15;          // 0..15
            int col = col0 + c4*4;
            float xs[4] = {0.f, 0.f, 0.f, 0.f};
            const float* bp = &B[(size_t)(k0 + r)*N + col];
            if (n4 && col + 3 < N) {
                float4 v = *reinterpret_cast<const float4*>(bp);
                xs[0] = v.x; xs[1] = v.y; xs[2] = v.z; xs[3] = v.w;
            } else {
                #pragma unroll
                for (int e = 0; e < 4; e++)
                    if (col + e < N) xs[e] = bp[e];
            }
            #pragma unroll
            for (int e = 0; e < 4; e++) {
                float hi = __uint_as_float(f2tf32(xs[e]));
                Bs[0][r][c4*4 + e] = hi;
                Bs[1][r][c4*4 + e] = xs[e] - hi;
            }
        }
        __syncthreads();

        // ---- compute: 2 k-steps of 8 ----
        #pragma unroll
        for (int ks = 0; ks < BK; ks += 8) {
            uint32_t ah[2][4], al[2][4];
            #pragma unroll
            for (int mt = 0; mt < 2; mt++) {
                int rb = wm*32 + mt*16;
                ah[mt][0] = __float_as_uint(As[0][ks + t4    ][rb + g    ]);
                ah[mt][1] = __float_as_uint(As[0][ks + t4    ][rb + g + 8]);
                ah[mt][2] = __float_as_uint(As[0][ks + t4 + 4][rb + g    ]);
                ah[mt][3] = __float_as_uint(As[0][ks + t4 + 4][rb + g + 8]);
                al[mt][0] = __float_as_uint(As[1][ks + t4    ][rb + g    ]);
                al[mt][1] = __float_as_uint(As[1][ks + t4    ][rb + g + 8]);
                al[mt][2] = __float_as_uint(As[1][ks + t4 + 4][rb + g    ]);
                al[mt][3] = __float_as_uint(As[1][ks + t4 + 4][rb + g + 8]);
            }
            uint32_t bh[4][2], bl[4][2];
            #pragma unroll
            for (int nt = 0; nt < 4; nt++) {
                int cb = wn*32 + nt*8 + g;
                bh[nt][0] = __float_as_uint(Bs[0][ks + t4    ][cb]);
                bh[nt][1] = __float_as_uint(Bs[0][ks + t4 + 4][cb]);
                bl[nt][0] = __float_as_uint(Bs[1][ks + t4    ][cb]);
                bl[nt][1] = __float_as_uint(Bs[1][ks + t4 + 4][cb]);
            }
            #pragma unroll
            for (int mt = 0; mt < 2; mt++)
                #pragma unroll
                for (int nt = 0; nt < 4; nt++) {
                    mma_tf32(acc[mt][nt], ah[mt], bh[nt]);  // hi*hi
                    mma_tf32(acc[mt][nt], ah[mt], bl[nt]);  // hi*lo
                    mma_tf32(acc[mt][nt], al[mt], bh[nt]);  // lo*hi
                }
        }
        __syncthreads();
    }

    // ---- epilogue ----
    #pragma unroll
    for (int mt = 0; mt < 2; mt++) {
        #pragma unroll
        for (int nt = 0; nt < 4; nt++) {
            #pragma unroll
            for (int i = 0; i < 4; i++) {
                int row = row0 + wm*32 + mt*16 + g + (i >> 1)*8;
                int col = col0 + wn*32 + nt*8 + 2*t4 + (i & 1);
                if (col >= N) continue;
                float v = acc[mt][nt][i];
                if (bias) v += bias[col];
                if (ACT == 1) v = 0.5f * v * (1.f + erff(v * 0.70710678118654752f));
                if (R) v += R[(size_t)row*N + col];
                C[(size_t)row*N + col] = v;
            }
        }
    }
}

// ---------------- fused causal attention: one block per (query, head) -----
__global__ void attn_kernel(const float* __restrict__ qkv,
                            float* __restrict__ z) {
    int s = blockIdx.x;
    int h = blockIdx.y;
    int tid = threadIdx.x;       // 256 threads
    __shared__ float qs[DH];
    __shared__ float sc[S];
    __shared__ float red[256];
    __shared__ float zacc[4][DH];

    if (tid < DH) qs[tid] = qkv[(size_t)s*QKVN + h*DH + tid];
    __syncthreads();

    int nk = s + 1;
    const float scale = 0.125f;  // 1/sqrt(64)

    for (int t = tid; t < nk; t += 256) {
        const float* kp = qkv + (size_t)t*QKVN + DM + h*DH;
        float d = 0.f;
        #pragma unroll
        for (int e = 0; e < DH; e++) d = fmaf(qs[e], kp[e], d);
        sc[t] = d * scale;
    }
    __syncthreads();

    float m = -1e30f;
    for (int t = tid; t < nk; t += 256) m = fmaxf(m, sc[t]);
    red[tid] = m; __syncthreads();
    for (int o = 128; o > 0; o >>= 1) {
        if (tid < o) red[tid] = fmaxf(red[tid], red[tid+o]);
        __syncthreads();
    }
    m = red[0];
    __syncthreads();

    float lsum = 0.f;
    for (int t = tid; t < nk; t += 256) {
        float p = expf(sc[t] - m);
        sc[t] = p;
        lsum += p;
    }
    red[tid] = lsum; __syncthreads();
    for (int o = 128; o > 0; o >>= 1) {
        if (tid < o) red[tid] += red[tid+o];
        __syncthreads();
    }
    float inv = 1.f / red[0];
    __syncthreads();

    int e = tid & 63, grp = tid >> 6;
    float acc = 0.f;
    for (int t = grp; t < nk; t += 4)
        acc = fmaf(sc[t], qkv[(size_t)t*QKVN + 2*DM + h*DH + e], acc);
    zacc[grp][e] = acc;
    __syncthreads();
    if (tid < DH)
        z[(size_t)s*DM + h*DH + tid] =
            (zacc[0][tid] + zacc[1][tid] + zacc[2][tid] + zacc[3][tid]) * inv;
}

// ---------------- plain copy ----------------
__global__ void copy_kernel(const float* __restrict__ src, float* __restrict__ dst, int n) {
    int i = blockIdx.x * 256 + threadIdx.x;
    if (i < n) dst[i] = src[i];
}

// ---------------- launcher ----------------
extern "C" void kernel_launch(void* const* d_in, const int* in_sizes, int n_in,
                              void* d_out, int out_size) {
    const int*   tokens = (const int*)  d_in[0];
    const float* W_E    = (const float*)d_in[1];
    const float* W_pos  = (const float*)d_in[2];
    const float* ln1_w  = (const float*)d_in[3];
    const float* ln1_b  = (const float*)d_in[4];
    const float* W_Q    = (const float*)d_in[5];
    const float* b_Q    = (const float*)d_in[6];
    const float* W_K    = (const float*)d_in[7];
    const float* b_K    = (const float*)d_in[8];
    const float* W_V    = (const float*)d_in[9];
    const float* b_V    = (const float*)d_in[10];
    const float* W_O    = (const float*)d_in[11];
    const float* b_O    = (const float*)d_in[12];
    const float* ln2_w  = (const float*)d_in[13];
    const float* ln2_b  = (const float*)d_in[14];
    const float* W_in   = (const float*)d_in[15];
    const float* b_in   = (const float*)d_in[16];
    const float* W_out  = (const float*)d_in[17];
    const float* b_out  = (const float*)d_in[18];
    const float* lnf_w  = (const float*)d_in[19];
    const float* lnf_b  = (const float*)d_in[20];
    const float* W_U    = (const float*)d_in[21];
    const float* b_U    = (const float*)d_in[22];

    float *p_resid, *p_x, *p_qkv, *p_z, *p_post, *p_wqkv, *p_bqkv;
    cudaGetSymbolAddress((void**)&p_resid, g_resid);
    cudaGetSymbolAddress((void**)&p_x,     g_x);
    cudaGetSymbolAddress((void**)&p_qkv,   g_qkv);
    cudaGetSymbolAddress((void**)&p_z,     g_z);
    cudaGetSymbolAddress((void**)&p_post,  g_post);
    cudaGetSymbolAddress((void**)&p_wqkv,  g_wqkv);
    cudaGetSymbolAddress((void**)&p_bqkv,  g_bqkv);

    float* out = (float*)d_out;

    embed_kernel<<<(S*DM + 255)/256, 256>>>(tokens, W_E, W_pos, p_resid);

    for (int l = 0; l < L; l++) {
        const float* wq = W_Q + (size_t)l*H*DM*DH;
        const float* wk = W_K + (size_t)l*H*DM*DH;
        const float* wv = W_V + (size_t)l*H*DM*DH;
        const float* wo = W_O + (size_t)l*H*DH*DM;
        const float* bq = b_Q + (size_t)l*H*DH;
        const float* bk = b_K + (size_t)l*H*DH;
        const float* bv = b_V + (size_t)l*H*DH;
        const float* bo = b_O + (size_t)l*DM;
        const float* l1w = ln1_w + (size_t)l*DM, *l1b = ln1_b + (size_t)l*DM;
        const float* l2w = ln2_w + (size_t)l*DM, *l2b = ln2_b + (size_t)l*DM;
        const float* wi = W_in  + (size_t)l*DM*DMLP;
        const float* bi = b_in  + (size_t)l*DMLP;
        const float* wu2= W_out + (size_t)l*DMLP*DM;
        const float* bo2= b_out + (size_t)l*DM;

        pack_qkv_kernel<<<(DM*DM + 255)/256, 256>>>(wq, wk, wv, bq, bk, bv);

        ln_kernel<<<S, 256>>>(p_resid, l1w, l1b, p_x);

        // qkv = x @ wqkv + bqkv   [2048, 3072]
        mma_gemm_kernel<0><<<dim3(QKVN/BN, S/BM), 256>>>(
            p_x, p_wqkv, p_bqkv, nullptr, p_qkv, S, QKVN, DM);

        attn_kernel<<<dim3(S, H), 256>>>(p_qkv, p_z);

        // resid = z @ W_O + b_O + resid
        mma_gemm_kernel<0><<<dim3(DM/BN, S/BM), 256>>>(
            p_z, wo, bo, p_resid, p_resid, S, DM, DM);

        ln_kernel<<<S, 256>>>(p_resid, l2w, l2b, p_x);

        // post = gelu(x @ W_in + b_in)   [2048, 4096]
        mma_gemm_kernel<1><<<dim3(DMLP/BN, S/BM), 256>>>(
            p_x, wi, bi, nullptr, p_post, S, DMLP, DM);

        // resid = post @ W_out + b_out + resid
        mma_gemm_kernel<0><<<dim3(DM/BN, S/BM), 256>>>(
            p_post, wu2, bo2, p_resid, p_resid, S, DM, DMLP);
    }

    ln_kernel<<<S, 256>>>(p_resid, lnf_w, lnf_b, p_x);
    mma_gemm_kernel<0><<<dim3((NV + BN - 1)/BN, S/BM), 256>>>(
        p_x, W_U, b_U, nullptr, out, S, NV, DM);

    const long long LOG_N  = (long long)S * NV;
    const long long RES_N  = (long long)S * DM;
    const long long POST_N = (long long)S * DMLP;
    long long osz = (long long)out_size;
    if (osz >= LOG_N + RES_N)
        copy_kernel<<<(int)((RES_N + 255)/256), 256>>>(p_resid, out + LOG_N, (int)RES_N);
    if (osz >= LOG_N + RES_N + POST_N)
        copy_kernel<<<(int)((POST_N + 255)/256), 256>>>(p_post, out + LOG_N + RES_N, (int)POST_N);
}

// round 4
// speedup vs baseline: 2.2450x; 2.2351x over previous
#include <cuda_runtime.h>
#include <cuda_bf16.h>
#include <math.h>
#include <stdint.h>

// ---------------- problem constants ----------------
#define S      2048
#define DM     1024
#define H      16
#define DH     64
#define DMLP   4096
#define NV     50257
#define L      2
#define QKVN   (3*DM)      // 3072

// ---------------- static scratch (no allocations allowed) ----------------
__device__ float g_resid[S*DM];       // 8 MB
__device__ float g_x[S*DM];           // 8 MB  (LN output)
__device__ float g_qkv[S*QKVN];       // 24 MB
__device__ float g_z[S*DM];           // 8 MB
__device__ float g_post[S*DMLP];      // 32 MB
__device__ float g_wqkv[DM*QKVN];     // 12 MB packed per-layer QKV weights
__device__ float g_bqkv[QKVN];

// ---------------- f32x2 packed helpers ----------------
__device__ __forceinline__ unsigned long long pk2(float lo, float hi) {
    unsigned long long r;
    asm("mov.b64 %0, {%1,%2};" : "=l"(r) : "f"(lo), "f"(hi));
    return r;
}
__device__ __forceinline__ void unpk2(unsigned long long v, float& lo, float& hi) {
    asm("mov.b64 {%0,%1}, %2;" : "=f"(lo), "=f"(hi) : "l"(v));
}
__device__ __forceinline__ unsigned long long fma2(unsigned long long a,
                                                   unsigned long long b,
                                                   unsigned long long c) {
    unsigned long long r;
    asm("fma.rn.f32x2 %0, %1, %2, %3;" : "=l"(r) : "l"(a), "l"(b), "l"(c));
    return r;
}
__device__ __forceinline__ unsigned long long mul2(unsigned long long a,
                                                   unsigned long long b) {
    unsigned long long r;
    asm("mul.rn.f32x2 %0, %1, %2;" : "=l"(r) : "l"(a), "l"(b));
    return r;
}

// ---------------- embed ----------------
__global__ void embed_kernel(const int* __restrict__ tok,
                             const float* __restrict__ WE,
                             const float* __restrict__ Wpos,
                             float* __restrict__ resid) {
    int i = blockIdx.x * 256 + threadIdx.x;
    if (i >= S*DM) return;
    int s = i >> 10;
    int d = i & (DM-1);
    resid[i] = WE[(size_t)tok[s]*DM + d] + Wpos[i];
}

// ---------------- layernorm (block per row) ----------------
__global__ void ln_kernel(const float* __restrict__ x,
                          const float* __restrict__ w,
                          const float* __restrict__ b,
                          float* __restrict__ y) {
    __shared__ float rs[256], rs2[256];
    int r = blockIdx.x, tid = threadIdx.x;
    const float* xr = x + (size_t)r*DM;
    float s = 0.f, s2 = 0.f;
    #pragma unroll
    for (int i = tid; i < DM; i += 256) { float v = xr[i]; s += v; s2 += v*v; }
    rs[tid] = s; rs2[tid] = s2; __syncthreads();
    for (int o = 128; o > 0; o >>= 1) {
        if (tid < o) { rs[tid] += rs[tid+o]; rs2[tid] += rs2[tid+o]; }
        __syncthreads();
    }
    float mu  = rs[0] * (1.f/DM);
    float var = rs2[0] * (1.f/DM) - mu*mu;
    float inv = rsqrtf(var + 1e-5f);
    float* yr = y + (size_t)r*DM;
    for (int i = tid; i < DM; i += 256)
        yr[i] = (xr[i] - mu) * inv * w[i] + b[i];
}

// ---------------- pack QKV weights for layer l into [DM, 3*DM] ----------------
__global__ void pack_qkv_kernel(const float* __restrict__ WQ,
                                const float* __restrict__ WK,
                                const float* __restrict__ WV,
                                const float* __restrict__ bQ,
                                const float* __restrict__ bK,
                                const float* __restrict__ bV) {
    int idx = blockIdx.x * 256 + threadIdx.x;
    if (idx >= DM*DM) return;
    int d = idx >> 10;          // DM row
    int c = idx & (DM-1);       // h*DH+e column
    int h = c >> 6, e = c & (DH-1);
    size_t src = ((size_t)h*DM + d)*DH + e;   // W[h][d][e]
    g_wqkv[(size_t)d*QKVN + c]        = WQ[src];
    g_wqkv[(size_t)d*QKVN + DM + c]   = WK[src];
    g_wqkv[(size_t)d*QKVN + 2*DM + c] = WV[src];
    if (idx < DM) {
        g_bqkv[idx]        = bQ[idx];
        g_bqkv[DM + idx]   = bK[idx];
        g_bqkv[2*DM + idx] = bV[idx];
    }
}

// ---------------- tf32 helpers ----------------
__device__ __forceinline__ uint32_t f2tf32(float x) {
    uint32_t r;
    asm("cvt.rna.tf32.f32 %0, %1;" : "=r"(r) : "f"(x));
    return r;
}

__device__ __forceinline__ void mma_tf32(float c[4],
                                         const uint32_t a[4],
                                         const uint32_t b[2]) {
    asm volatile(
        "mma.sync.aligned.m16n8k8.row.col.f32.tf32.tf32.f32 "
        "{%0,%1,%2,%3}, {%4,%5,%6,%7}, {%8,%9}, {%0,%1,%2,%3};\n"
        : "+f"(c[0]), "+f"(c[1]), "+f"(c[2]), "+f"(c[3])
        : "r"(a[0]), "r"(a[1]), "r"(a[2]), "r"(a[3]),
          "r"(b[0]), "r"(b[1]));
}

// ---------------- tensor-core GEMM with 3xTF32 split ------------------
#define BM 128
#define BN 64
#define BK 16
#define ASTR (BM+4)
#define BSTR (BN+4)

template <int ACT>
__global__ __launch_bounds__(256, 2)
void mma_gemm_kernel(const float* __restrict__ A,
                     const float* __restrict__ B,
                     const float* __restrict__ bias,
                     const float* __restrict__ R,
                     float* __restrict__ C,
                     int M, int N, int K) {
    __shared__ float As[2][BK][ASTR];   // [hi/lo][k][m]
    __shared__ float Bs[2][BK][BSTR];   // [hi/lo][k][n]

    const int tid  = threadIdx.x;
    const int lane = tid & 31;
    const int wid  = tid >> 5;
    const int g    = lane >> 2;
    const int t4   = lane & 3;
    const int wm   = wid >> 1;
    const int wn   = wid & 1;
    const int row0 = blockIdx.y * BM;
    const int col0 = blockIdx.x * BN;
    const bool n4  = (N & 3) == 0;

    float acc[2][4][4];
    #pragma unroll
    for (int mt = 0; mt < 2; mt++)
        #pragma unroll
        for (int nt = 0; nt < 4; nt++)
            #pragma unroll
            for (int i = 0; i < 4; i++) acc[mt][nt][i] = 0.f;

    for (int k0 = 0; k0 < K; k0 += BK) {
        #pragma unroll
        for (int t = 0; t < 2; t++) {
            int idx = tid + t*256;
            int r   = idx >> 2;
            int c4  = idx & 3;
            float4 v = *reinterpret_cast<const float4*>(
                &A[(size_t)(row0 + r)*K + k0 + c4*4]);
            float xs[4] = {v.x, v.y, v.z, v.w};
            #pragma unroll
            for (int e = 0; e < 4; e++) {
                float hi = __uint_as_float(f2tf32(xs[e]));
                As[0][c4*4 + e][r] = hi;
                As[1][c4*4 + e][r] = xs[e] - hi;
            }
        }
        {
            int r  = tid >> 4;
            int c4 = tid & 15;
            int col = col0 + c4*4;
            float xs[4] = {0.f, 0.f, 0.f, 0.f};
            const float* bp = &B[(size_t)(k0 + r)*N + col];
            if (n4 && col + 3 < N) {
                float4 v = *reinterpret_cast<const float4*>(bp);
                xs[0] = v.x; xs[1] = v.y; xs[2] = v.z; xs[3] = v.w;
            } else {
                #pragma unroll
                for (int e = 0; e < 4; e++)
                    if (col + e < N) xs[e] = bp[e];
            }
            #pragma unroll
            for (int e = 0; e < 4; e++) {
                float hi = __uint_as_float(f2tf32(xs[e]));
                Bs[0][r][c4*4 + e] = hi;
                Bs[1][r][c4*4 + e] = xs[e] - hi;
            }
        }
        __syncthreads();

        #pragma unroll
        for (int ks = 0; ks < BK; ks += 8) {
            uint32_t ah[2][4], al[2][4];
            #pragma unroll
            for (int mt = 0; mt < 2; mt++) {
                int rb = wm*32 + mt*16;
                ah[mt][0] = __float_as_uint(As[0][ks + t4    ][rb + g    ]);
                ah[mt][1] = __float_as_uint(As[0][ks + t4    ][rb + g + 8]);
                ah[mt][2] = __float_as_uint(As[0][ks + t4 + 4][rb + g    ]);
                ah[mt][3] = __float_as_uint(As[0][ks + t4 + 4][rb + g + 8]);
                al[mt][0] = __float_as_uint(As[1][ks + t4    ][rb + g    ]);
                al[mt][1] = __float_as_uint(As[1][ks + t4    ][rb + g + 8]);
                al[mt][2] = __float_as_uint(As[1][ks + t4 + 4][rb + g    ]);
                al[mt][3] = __float_as_uint(As[1][ks + t4 + 4][rb + g + 8]);
            }
            uint32_t bh[4][2], bl[4][2];
            #pragma unroll
            for (int nt = 0; nt < 4; nt++) {
                int cb = wn*32 + nt*8 + g;
                bh[nt][0] = __float_as_uint(Bs[0][ks + t4    ][cb]);
                bh[nt][1] = __float_as_uint(Bs[0][ks + t4 + 4][cb]);
                bl[nt][0] = __float_as_uint(Bs[1][ks + t4    ][cb]);
                bl[nt][1] = __float_as_uint(Bs[1][ks + t4 + 4][cb]);
            }
            #pragma unroll
            for (int mt = 0; mt < 2; mt++)
                #pragma unroll
                for (int nt = 0; nt < 4; nt++) {
                    mma_tf32(acc[mt][nt], ah[mt], bh[nt]);
                    mma_tf32(acc[mt][nt], ah[mt], bl[nt]);
                    mma_tf32(acc[mt][nt], al[mt], bh[nt]);
                }
        }
        __syncthreads();
    }

    #pragma unroll
    for (int mt = 0; mt < 2; mt++) {
        #pragma unroll
        for (int nt = 0; nt < 4; nt++) {
            #pragma unroll
            for (int i = 0; i < 4; i++) {
                int row = row0 + wm*32 + mt*16 + g + (i >> 1)*8;
                int col = col0 + wn*32 + nt*8 + 2*t4 + (i & 1);
                if (col >= N) continue;
                float v = acc[mt][nt][i];
                if (bias) v += bias[col];
                if (ACT == 1) v = 0.5f * v * (1.f + erff(v * 0.70710678118654752f));
                if (R) v += R[(size_t)row*N + col];
                C[(size_t)row*N + col] = v;
            }
        }
    }
}

// ---------------- flash attention: thread-per-query, f32x2 packed ---------
// Block: 128 threads = 128 queries for one head. Key/value tiles of 64 rows
// staged in smem as packed f32x2 (ull). Online softmax with rare-rescale.
#define KT 64
__global__ __launch_bounds__(128)
void attn_flash_kernel(const float* __restrict__ qkv,
                       float* __restrict__ z) {
    // reversed q-tile order: heaviest (largest q) blocks launch first
    const int qt  = (gridDim.x - 1) - blockIdx.x;
    const int h   = blockIdx.y;
    const int tid = threadIdx.x;
    const int q   = qt*128 + tid;
    const int qmax = qt*128 + 127;

    __shared__ unsigned long long Ks[KT][33];   // padded: conflict-free fills
    __shared__ unsigned long long Vs[KT][33];

    // load this thread's q row (64 floats) packed into 32 ull
    unsigned long long qp[32];
    {
        const float4* qrow = reinterpret_cast<const float4*>(
            qkv + (size_t)q*QKVN + h*DH);
        #pragma unroll
        for (int i = 0; i < 16; i++) {
            float4 v = qrow[i];
            qp[2*i]   = pk2(v.x, v.y);
            qp[2*i+1] = pk2(v.z, v.w);
        }
    }
    unsigned long long accp[32];
    #pragma unroll
    for (int i = 0; i < 32; i++) accp[i] = 0ULL;
    float m = -1e30f, lsum = 0.f;

    const int row  = tid >> 1;     // tile-fill row (0..63)
    const int half = tid & 1;      // tile-fill half

    for (int t0 = 0; t0 <= qmax; t0 += KT) {
        __syncthreads();   // previous tile fully consumed
        // cooperative fill: 2 threads per row, 32 floats each
        {
            const float4* ksrc = reinterpret_cast<const float4*>(
                qkv + (size_t)(t0 + row)*QKVN + DM + h*DH + half*32);
            const float4* vsrc = reinterpret_cast<const float4*>(
                qkv + (size_t)(t0 + row)*QKVN + 2*DM + h*DH + half*32);
            #pragma unroll
            for (int j = 0; j < 8; j++) {
                float4 kv = ksrc[j];
                Ks[row][half*16 + 2*j]     = pk2(kv.x, kv.y);
                Ks[row][half*16 + 2*j + 1] = pk2(kv.z, kv.w);
                float4 vv = vsrc[j];
                Vs[row][half*16 + 2*j]     = pk2(vv.x, vv.y);
                Vs[row][half*16 + 2*j + 1] = pk2(vv.z, vv.w);
            }
        }
        __syncthreads();

        int len = q + 1 - t0;
        if (len > KT) len = KT;
        for (int t = 0; t < len; t++) {
            const unsigned long long* kr = Ks[t];
            unsigned long long d0 = 0ULL, d1 = 0ULL, d2 = 0ULL, d3 = 0ULL;
            #pragma unroll
            for (int i = 0; i < 8; i++) {
                d0 = fma2(qp[4*i    ], kr[4*i    ], d0);
                d1 = fma2(qp[4*i + 1], kr[4*i + 1], d1);
                d2 = fma2(qp[4*i + 2], kr[4*i + 2], d2);
                d3 = fma2(qp[4*i + 3], kr[4*i + 3], d3);
            }
            float a0, a1, b0, b1, c0, c1, e0, e1;
            unpk2(d0, a0, a1); unpk2(d1, b0, b1);
            unpk2(d2, c0, c1); unpk2(d3, e0, e1);
            float sc = ((a0 + a1) + (b0 + b1)) + ((c0 + c1) + (e0 + e1));
            sc *= 0.125f;                       // 1/sqrt(64)

            float p;
            if (sc > m) {                       // rare: new running max
                float r = __expf(m - sc);
                unsigned long long r2 = pk2(r, r);
                #pragma unroll
                for (int i = 0; i < 32; i++) accp[i] = mul2(accp[i], r2);
                lsum *= r;
                m = sc;
                p = 1.f;
            } else {
                p = __expf(sc - m);
            }
            lsum += p;
            unsigned long long pp = pk2(p, p);
            const unsigned long long* vr = Vs[t];
            #pragma unroll
            for (int i = 0; i < 32; i++)
                accp[i] = fma2(pp, vr[i], accp[i]);
        }
    }

    float inv = 1.f / lsum;
    float2* zrow = reinterpret_cast<float2*>(z + (size_t)q*DM + h*DH);
    #pragma unroll
    for (int i = 0; i < 32; i++) {
        float x0, x1;
        unpk2(accp[i], x0, x1);
        zrow[i] = make_float2(x0 * inv, x1 * inv);
    }
}

// ---------------- plain copy ----------------
__global__ void copy_kernel(const float* __restrict__ src, float* __restrict__ dst, int n) {
    int i = blockIdx.x * 256 + threadIdx.x;
    if (i < n) dst[i] = src[i];
}

// ---------------- launcher ----------------
extern "C" void kernel_launch(void* const* d_in, const int* in_sizes, int n_in,
                              void* d_out, int out_size) {
    const int*   tokens = (const int*)  d_in[0];
    const float* W_E    = (const float*)d_in[1];
    const float* W_pos  = (const float*)d_in[2];
    const float* ln1_w  = (const float*)d_in[3];
    const float* ln1_b  = (const float*)d_in[4];
    const float* W_Q    = (const float*)d_in[5];
    const float* b_Q    = (const float*)d_in[6];
    const float* W_K    = (const float*)d_in[7];
    const float* b_K    = (const float*)d_in[8];
    const float* W_V    = (const float*)d_in[9];
    const float* b_V    = (const float*)d_in[10];
    const float* W_O    = (const float*)d_in[11];
    const float* b_O    = (const float*)d_in[12];
    const float* ln2_w  = (const float*)d_in[13];
    const float* ln2_b  = (const float*)d_in[14];
    const float* W_in   = (const float*)d_in[15];
    const float* b_in   = (const float*)d_in[16];
    const float* W_out  = (const float*)d_in[17];
    const float* b_out  = (const float*)d_in[18];
    const float* lnf_w  = (const float*)d_in[19];
    const float* lnf_b  = (const float*)d_in[20];
    const float* W_U    = (const float*)d_in[21];
    const float* b_U    = (const float*)d_in[22];

    float *p_resid, *p_x, *p_qkv, *p_z, *p_post, *p_wqkv, *p_bqkv;
    cudaGetSymbolAddress((void**)&p_resid, g_resid);
    cudaGetSymbolAddress((void**)&p_x,     g_x);
    cudaGetSymbolAddress((void**)&p_qkv,   g_qkv);
    cudaGetSymbolAddress((void**)&p_z,     g_z);
    cudaGetSymbolAddress((void**)&p_post,  g_post);
    cudaGetSymbolAddress((void**)&p_wqkv,  g_wqkv);
    cudaGetSymbolAddress((void**)&p_bqkv,  g_bqkv);

    float* out = (float*)d_out;

    embed_kernel<<<(S*DM + 255)/256, 256>>>(tokens, W_E, W_pos, p_resid);

    for (int l = 0; l < L; l++) {
        const float* wq = W_Q + (size_t)l*H*DM*DH;
        const float* wk = W_K + (size_t)l*H*DM*DH;
        const float* wv = W_V + (size_t)l*H*DM*DH;
        const float* wo = W_O + (size_t)l*H*DH*DM;
        const float* bq = b_Q + (size_t)l*H*DH;
        const float* bk = b_K + (size_t)l*H*DH;
        const float* bv = b_V + (size_t)l*H*DH;
        const float* bo = b_O + (size_t)l*DM;
        const float* l1w = ln1_w + (size_t)l*DM, *l1b = ln1_b + (size_t)l*DM;
        const float* l2w = ln2_w + (size_t)l*DM, *l2b = ln2_b + (size_t)l*DM;
        const float* wi = W_in  + (size_t)l*DM*DMLP;
        const float* bi = b_in  + (size_t)l*DMLP;
        const float* wu2= W_out + (size_t)l*DMLP*DM;
        const float* bo2= b_out + (size_t)l*DM;

        pack_qkv_kernel<<<(DM*DM + 255)/256, 256>>>(wq, wk, wv, bq, bk, bv);

        ln_kernel<<<S, 256>>>(p_resid, l1w, l1b, p_x);

        // qkv = x @ wqkv + bqkv   [2048, 3072]
        mma_gemm_kernel<0><<<dim3(QKVN/BN, S/BM), 256>>>(
            p_x, p_wqkv, p_bqkv, nullptr, p_qkv, S, QKVN, DM);

        // flash attention
        attn_flash_kernel<<<dim3(S/128, H), 128>>>(p_qkv, p_z);

        // resid = z @ W_O + b_O + resid
        mma_gemm_kernel<0><<<dim3(DM/BN, S/BM), 256>>>(
            p_z, wo, bo, p_resid, p_resid, S, DM, DM);

        ln_kernel<<<S, 256>>>(p_resid, l2w, l2b, p_x);

        // post = gelu(x @ W_in + b_in)   [2048, 4096]
        mma_gemm_kernel<1><<<dim3(DMLP/BN, S/BM), 256>>>(
            p_x, wi, bi, nullptr, p_post, S, DMLP, DM);

        // resid = post @ W_out + b_out + resid
        mma_gemm_kernel<0><<<dim3(DM/BN, S/BM), 256>>>(
            p_post, wu2, bo2, p_resid, p_resid, S, DM, DMLP);
    }

    ln_kernel<<<S, 256>>>(p_resid, lnf_w, lnf_b, p_x);
    mma_gemm_kernel<0><<<dim3((NV + BN - 1)/BN, S/BM), 256>>>(
        p_x, W_U, b_U, nullptr, out, S, NV, DM);

    const long long LOG_N  = (long long)S * NV;
    const long long RES_N  = (long long)S * DM;
    const long long POST_N = (long long)S * DMLP;
    long long osz = (long long)out_size;
    if (osz >= LOG_N + RES_N)
        copy_kernel<<<(int)((RES_N + 255)/256), 256>>>(p_resid, out + LOG_N, (int)RES_N);
    if (osz >= LOG_N + RES_N + POST_N)
        copy_kernel<<<(int)((POST_N + 255)/256), 256>>>(p_post, out + LOG_N + RES_N, (int)POST_N);
}

// round 5
// speedup vs baseline: 4.0841x; 1.8192x over previous
#include <cuda_runtime.h>
#include <cuda_bf16.h>
#include <math.h>
#include <stdint.h>

// ---------------- problem constants ----------------
#define S      2048
#define DM     1024
#define H      16
#define DH     64
#define DMLP   4096
#define NV     50257
#define L      2
#define QKVN   (3*DM)      // 3072

// ---------------- static scratch (no allocations allowed) ----------------
__device__ float g_resid[S*DM];
__device__ float g_x[S*DM];
__device__ float g_qkv[S*QKVN];
__device__ float g_z[S*DM];
__device__ float g_post[S*DMLP];
__device__ float g_wqkv[DM*QKVN];
__device__ float g_bqkv[QKVN];

// ---------------- f32x2 packed helpers (attention) ----------------
__device__ __forceinline__ unsigned long long pk2(float lo, float hi) {
    unsigned long long r;
    asm("mov.b64 %0, {%1,%2};" : "=l"(r) : "f"(lo), "f"(hi));
    return r;
}
__device__ __forceinline__ void unpk2(unsigned long long v, float& lo, float& hi) {
    asm("mov.b64 {%0,%1}, %2;" : "=f"(lo), "=f"(hi) : "l"(v));
}
__device__ __forceinline__ unsigned long long fma2(unsigned long long a,
                                                   unsigned long long b,
                                                   unsigned long long c) {
    unsigned long long r;
    asm("fma.rn.f32x2 %0, %1, %2, %3;" : "=l"(r) : "l"(a), "l"(b), "l"(c));
    return r;
}
__device__ __forceinline__ unsigned long long mul2(unsigned long long a,
                                                   unsigned long long b) {
    unsigned long long r;
    asm("mul.rn.f32x2 %0, %1, %2;" : "=l"(r) : "l"(a), "l"(b));
    return r;
}

// ---------------- embed ----------------
__global__ void embed_kernel(const int* __restrict__ tok,
                             const float* __restrict__ WE,
                             const float* __restrict__ Wpos,
                             float* __restrict__ resid) {
    int i = blockIdx.x * 256 + threadIdx.x;
    if (i >= S*DM) return;
    int s = i >> 10;
    int d = i & (DM-1);
    resid[i] = WE[(size_t)tok[s]*DM + d] + Wpos[i];
}

// ---------------- layernorm ----------------
__global__ void ln_kernel(const float* __restrict__ x,
                          const float* __restrict__ w,
                          const float* __restrict__ b,
                          float* __restrict__ y) {
    __shared__ float rs[256], rs2[256];
    int r = blockIdx.x, tid = threadIdx.x;
    const float* xr = x + (size_t)r*DM;
    float s = 0.f, s2 = 0.f;
    #pragma unroll
    for (int i = tid; i < DM; i += 256) { float v = xr[i]; s += v; s2 += v*v; }
    rs[tid] = s; rs2[tid] = s2; __syncthreads();
    for (int o = 128; o > 0; o >>= 1) {
        if (tid < o) { rs[tid] += rs[tid+o]; rs2[tid] += rs2[tid+o]; }
        __syncthreads();
    }
    float mu  = rs[0] * (1.f/DM);
    float var = rs2[0] * (1.f/DM) - mu*mu;
    float inv = rsqrtf(var + 1e-5f);
    float* yr = y + (size_t)r*DM;
    for (int i = tid; i < DM; i += 256)
        yr[i] = (xr[i] - mu) * inv * w[i] + b[i];
}

// ---------------- pack QKV weights ----------------
__global__ void pack_qkv_kernel(const float* __restrict__ WQ,
                                const float* __restrict__ WK,
                                const float* __restrict__ WV,
                                const float* __restrict__ bQ,
                                const float* __restrict__ bK,
                                const float* __restrict__ bV) {
    int idx = blockIdx.x * 256 + threadIdx.x;
    if (idx >= DM*DM) return;
    int d = idx >> 10;
    int c = idx & (DM-1);
    int h = c >> 6, e = c & (DH-1);
    size_t src = ((size_t)h*DM + d)*DH + e;
    g_wqkv[(size_t)d*QKVN + c]        = WQ[src];
    g_wqkv[(size_t)d*QKVN + DM + c]   = WK[src];
    g_wqkv[(size_t)d*QKVN + 2*DM + c] = WV[src];
    if (idx < DM) {
        g_bqkv[idx]        = bQ[idx];
        g_bqkv[DM + idx]   = bK[idx];
        g_bqkv[2*DM + idx] = bV[idx];
    }
}

// ---------------- bf16 split helpers ----------------
// pack two floats (k, k+1 order) into one .b32 of bf16 hi parts, and one of lo parts
__device__ __forceinline__ void split_pack(float x0, float x1,
                                           uint32_t& hi, uint32_t& lo) {
    __nv_bfloat16 h0 = __float2bfloat16_rn(x0);
    __nv_bfloat16 h1 = __float2bfloat16_rn(x1);
    float r0 = x0 - __bfloat162float(h0);
    float r1 = x1 - __bfloat162float(h1);
    __nv_bfloat16 l0 = __float2bfloat16_rn(r0);
    __nv_bfloat16 l1 = __float2bfloat16_rn(r1);
    __nv_bfloat162 hp = __halves2bfloat162(h0, h1);   // h0 -> low 16 bits
    __nv_bfloat162 lp = __halves2bfloat162(l0, l1);
    hi = *reinterpret_cast<uint32_t*>(&hp);
    lo = *reinterpret_cast<uint32_t*>(&lp);
}

__device__ __forceinline__ void mma_bf16(float c[4],
                                         const uint32_t a[4],
                                         const uint32_t b[2]) {
    asm volatile(
        "mma.sync.aligned.m16n8k16.row.col.f32.bf16.bf16.f32 "
        "{%0,%1,%2,%3}, {%4,%5,%6,%7}, {%8,%9}, {%0,%1,%2,%3};\n"
        : "+f"(c[0]), "+f"(c[1]), "+f"(c[2]), "+f"(c[3])
        : "r"(a[0]), "r"(a[1]), "r"(a[2]), "r"(a[3]),
          "r"(b[0]), "r"(b[1]));
}

// ---------------- bf16x3 tensor-core GEMM, 2-stage pipelined ------------
// C = act(A@B + bias) (+ R).  A:[M,K] rm, B:[K,N] rm.  M%128==0, K%16==0.
#define BM 128
#define BN 64
#define BK 16
#define ASTR 136   // %32 == 8 -> conflict-free fragment LDS
#define BSTR 72    // %32 == 8

template <int ACT>
__global__ __launch_bounds__(256, 2)
void mma_gemm_kernel(const float* __restrict__ A,
                     const float* __restrict__ B,
                     const float* __restrict__ bias,
                     const float* __restrict__ R,
                     float* __restrict__ C,
                     int M, int N, int K) {
    // [buf][kpair][m or n] ; kpair = k/2 (0..7)
    __shared__ uint32_t AsH[2][8][ASTR], AsL[2][8][ASTR];
    __shared__ uint32_t BsH[2][8][BSTR], BsL[2][8][BSTR];

    const int tid  = threadIdx.x;
    const int lane = tid & 31;
    const int wid  = tid >> 5;
    const int g    = lane >> 2;
    const int t4   = lane & 3;
    const int wm   = wid >> 1;          // 0..3
    const int wn   = wid & 1;           // 0..1
    const int row0 = blockIdx.y * BM;
    const int col0 = blockIdx.x * BN;
    const bool n2  = (N & 1) == 0;

    // staging coords
    const int ar0 = tid >> 2;           // A row for idx = tid      (0..63)
    const int ar1 = (tid + 256) >> 2;   // A row for idx = tid+256  (64..127)
    const int ac4 = tid & 3;            // A k-group (float4 index)
    const int bkp = tid >> 5;           // B kpair 0..7
    const int bn0 = (lane) * 2;         // B local col 0..62

    float acc[2][4][4];
    #pragma unroll
    for (int mt = 0; mt < 2; mt++)
        #pragma unroll
        for (int nt = 0; nt < 4; nt++)
            #pragma unroll
            for (int i = 0; i < 4; i++) acc[mt][nt][i] = 0.f;

    float4 av[2];
    float  bv[4];

    // ---- gmem fetch of one BK tile into registers ----
    auto fetch = [&](int k0) {
        av[0] = *reinterpret_cast<const float4*>(
            &A[(size_t)(row0 + ar0)*K + k0 + ac4*4]);
        av[1] = *reinterpret_cast<const float4*>(
            &A[(size_t)(row0 + ar1)*K + k0 + ac4*4]);
        int c0 = col0 + bn0, c1 = col0 + bn0 + 1;
        const float* b0p = &B[(size_t)(k0 + 2*bkp)*N];
        const float* b1p = &B[(size_t)(k0 + 2*bkp + 1)*N];
        if (n2) {
            float2 u = *reinterpret_cast<const float2*>(b0p + c0);
            float2 w = *reinterpret_cast<const float2*>(b1p + c0);
            bv[0] = u.x; bv[1] = u.y; bv[2] = w.x; bv[3] = w.y;
        } else {
            bv[0] = (c0 < N) ? b0p[c0] : 0.f;
            bv[1] = (c1 < N) ? b0p[c1] : 0.f;
            bv[2] = (c0 < N) ? b1p[c0] : 0.f;
            bv[3] = (c1 < N) ? b1p[c1] : 0.f;
        }
    };

    // ---- convert regs -> smem buf ----
    auto store = [&](int buf) {
        #pragma unroll
        for (int t = 0; t < 2; t++) {
            int r = (t == 0) ? ar0 : ar1;
            float xs[4] = {av[t].x, av[t].y, av[t].z, av[t].w};
            #pragma unroll
            for (int e = 0; e < 2; e++) {
                uint32_t hi, lo;
                split_pack(xs[2*e], xs[2*e+1], hi, lo);
                AsH[buf][ac4*2 + e][r] = hi;
                AsL[buf][ac4*2 + e][r] = lo;
            }
        }
        // B: pack along k: pair (k=2kp, k=2kp+1) per column
        uint32_t h0, l0, h1, l1;
        split_pack(bv[0], bv[2], h0, l0);   // col bn0
        split_pack(bv[1], bv[3], h1, l1);   // col bn0+1
        BsH[buf][bkp][bn0]     = h0;
        BsH[buf][bkp][bn0 + 1] = h1;
        BsL[buf][bkp][bn0]     = l0;
        BsL[buf][bkp][bn0 + 1] = l1;
    };

    fetch(0);
    store(0);
    __syncthreads();
    int cur = 0;

    for (int k0 = 0; k0 < K; k0 += BK) {
        bool has_next = (k0 + BK) < K;
        if (has_next) fetch(k0 + BK);

        // ---- fragments ----
        uint32_t ah[2][4], al[2][4];
        #pragma unroll
        for (int mt = 0; mt < 2; mt++) {
            int rb = wm*32 + mt*16;
            ah[mt][0] = AsH[cur][t4    ][rb + g    ];
            ah[mt][1] = AsH[cur][t4    ][rb + g + 8];
            ah[mt][2] = AsH[cur][t4 + 4][rb + g    ];
            ah[mt][3] = AsH[cur][t4 + 4][rb + g + 8];
            al[mt][0] = AsL[cur][t4    ][rb + g    ];
            al[mt][1] = AsL[cur][t4    ][rb + g + 8];
            al[mt][2] = AsL[cur][t4 + 4][rb + g    ];
            al[mt][3] = AsL[cur][t4 + 4][rb + g + 8];
        }
        uint32_t bh[4][2], bl[4][2];
        #pragma unroll
        for (int nt = 0; nt < 4; nt++) {
            int cb = wn*32 + nt*8 + g;
            bh[nt][0] = BsH[cur][t4    ][cb];
            bh[nt][1] = BsH[cur][t4 + 4][cb];
            bl[nt][0] = BsL[cur][t4    ][cb];
            bl[nt][1] = BsL[cur][t4 + 4][cb];
        }
        #pragma unroll
        for (int mt = 0; mt < 2; mt++)
            #pragma unroll
            for (int nt = 0; nt < 4; nt++) {
                mma_bf16(acc[mt][nt], ah[mt], bh[nt]);   // hi*hi
                mma_bf16(acc[mt][nt], ah[mt], bl[nt]);   // hi*lo
                mma_bf16(acc[mt][nt], al[mt], bh[nt]);   // lo*hi
            }

        if (has_next) {
            store(cur ^ 1);
            __syncthreads();
            cur ^= 1;
        }
    }

    // ---- epilogue ----
    #pragma unroll
    for (int mt = 0; mt < 2; mt++) {
        #pragma unroll
        for (int nt = 0; nt < 4; nt++) {
            #pragma unroll
            for (int i = 0; i < 4; i++) {
                int row = row0 + wm*32 + mt*16 + g + (i >> 1)*8;
                int col = col0 + wn*32 + nt*8 + 2*t4 + (i & 1);
                if (col >= N) continue;
                float v = acc[mt][nt][i];
                if (bias) v += bias[col];
                if (ACT == 1) v = 0.5f * v * (1.f + erff(v * 0.70710678118654752f));
                if (R) v += R[(size_t)row*N + col];
                C[(size_t)row*N + col] = v;
            }
        }
    }
}

// ---------------- flash attention: thread-per-query, f32x2 packed ---------
#define KT 64
__global__ __launch_bounds__(128)
void attn_flash_kernel(const float* __restrict__ qkv,
                       float* __restrict__ z) {
    const int qt  = (gridDim.x - 1) - blockIdx.x;
    const int h   = blockIdx.y;
    const int tid = threadIdx.x;
    const int q   = qt*128 + tid;
    const int qmax = qt*128 + 127;

    __shared__ unsigned long long Ks[KT][33];
    __shared__ unsigned long long Vs[KT][33];

    unsigned long long qp[32];
    {
        const float4* qrow = reinterpret_cast<const float4*>(
            qkv + (size_t)q*QKVN + h*DH);
        #pragma unroll
        for (int i = 0; i < 16; i++) {
            float4 v = qrow[i];
            qp[2*i]   = pk2(v.x, v.y);
            qp[2*i+1] = pk2(v.z, v.w);
        }
    }
    unsigned long long accp[32];
    #pragma unroll
    for (int i = 0; i < 32; i++) accp[i] = 0ULL;
    float m = -1e30f, lsum = 0.f;

    const int row  = tid >> 1;
    const int half = tid & 1;

    for (int t0 = 0; t0 <= qmax; t0 += KT) {
        __syncthreads();
        {
            const float4* ksrc = reinterpret_cast<const float4*>(
                qkv + (size_t)(t0 + row)*QKVN + DM + h*DH + half*32);
            const float4* vsrc = reinterpret_cast<const float4*>(
                qkv + (size_t)(t0 + row)*QKVN + 2*DM + h*DH + half*32);
            #pragma unroll
            for (int j = 0; j < 8; j++) {
                float4 kv = ksrc[j];
                Ks[row][half*16 + 2*j]     = pk2(kv.x, kv.y);
                Ks[row][half*16 + 2*j + 1] = pk2(kv.z, kv.w);
                float4 vv = vsrc[j];
                Vs[row][half*16 + 2*j]     = pk2(vv.x, vv.y);
                Vs[row][half*16 + 2*j + 1] = pk2(vv.z, vv.w);
            }
        }
        __syncthreads();

        int len = q + 1 - t0;
        if (len > KT) len = KT;
        for (int t = 0; t < len; t++) {
            const unsigned long long* kr = Ks[t];
            unsigned long long d0 = 0ULL, d1 = 0ULL, d2 = 0ULL, d3 = 0ULL;
            #pragma unroll
            for (int i = 0; i < 8; i++) {
                d0 = fma2(qp[4*i    ], kr[4*i    ], d0);
                d1 = fma2(qp[4*i + 1], kr[4*i + 1], d1);
                d2 = fma2(qp[4*i + 2], kr[4*i + 2], d2);
                d3 = fma2(qp[4*i + 3], kr[4*i + 3], d3);
            }
            float a0, a1, b0, b1, c0, c1, e0, e1;
            unpk2(d0, a0, a1); unpk2(d1, b0, b1);
            unpk2(d2, c0, c1); unpk2(d3, e0, e1);
            float sc = ((a0 + a1) + (b0 + b1)) + ((c0 + c1) + (e0 + e1));
            sc *= 0.125f;

            float p;
            if (sc > m) {
                float r = __expf(m - sc);
                unsigned long long r2 = pk2(r, r);
                #pragma unroll
                for (int i = 0; i < 32; i++) accp[i] = mul2(accp[i], r2);
                lsum *= r;
                m = sc;
                p = 1.f;
            } else {
                p = __expf(sc - m);
            }
            lsum += p;
            unsigned long long pp = pk2(p, p);
            const unsigned long long* vr = Vs[t];
            #pragma unroll
            for (int i = 0; i < 32; i++)
                accp[i] = fma2(pp, vr[i], accp[i]);
        }
    }

    float inv = 1.f / lsum;
    float2* zrow = reinterpret_cast<float2*>(z + (size_t)q*DM + h*DH);
    #pragma unroll
    for (int i = 0; i < 32; i++) {
        float x0, x1;
        unpk2(accp[i], x0, x1);
        zrow[i] = make_float2(x0 * inv, x1 * inv);
    }
}

// ---------------- plain copy ----------------
__global__ void copy_kernel(const float* __restrict__ src, float* __restrict__ dst, int n) {
    int i = blockIdx.x * 256 + threadIdx.x;
    if (i < n) dst[i] = src[i];
}

// ---------------- launcher ----------------
extern "C" void kernel_launch(void* const* d_in, const int* in_sizes, int n_in,
                              void* d_out, int out_size) {
    const int*   tokens = (const int*)  d_in[0];
    const float* W_E    = (const float*)d_in[1];
    const float* W_pos  = (const float*)d_in[2];
    const float* ln1_w  = (const float*)d_in[3];
    const float* ln1_b  = (const float*)d_in[4];
    const float* W_Q    = (const float*)d_in[5];
    const float* b_Q    = (const float*)d_in[6];
    const float* W_K    = (const float*)d_in[7];
    const float* b_K    = (const float*)d_in[8];
    const float* W_V    = (const float*)d_in[9];
    const float* b_V    = (const float*)d_in[10];
    const float* W_O    = (const float*)d_in[11];
    const float* b_O    = (const float*)d_in[12];
    const float* ln2_w  = (const float*)d_in[13];
    const float* ln2_b  = (const float*)d_in[14];
    const float* W_in   = (const float*)d_in[15];
    const float* b_in   = (const float*)d_in[16];
    const float* W_out  = (const float*)d_in[17];
    const float* b_out  = (const float*)d_in[18];
    const float* lnf_w  = (const float*)d_in[19];
    const float* lnf_b  = (const float*)d_in[20];
    const float* W_U    = (const float*)d_in[21];
    const float* b_U    = (const float*)d_in[22];

    float *p_resid, *p_x, *p_qkv, *p_z, *p_post, *p_wqkv, *p_bqkv;
    cudaGetSymbolAddress((void**)&p_resid, g_resid);
    cudaGetSymbolAddress((void**)&p_x,     g_x);
    cudaGetSymbolAddress((void**)&p_qkv,   g_qkv);
    cudaGetSymbolAddress((void**)&p_z,     g_z);
    cudaGetSymbolAddress((void**)&p_post,  g_post);
    cudaGetSymbolAddress((void**)&p_wqkv,  g_wqkv);
    cudaGetSymbolAddress((void**)&p_bqkv,  g_bqkv);

    float* out = (float*)d_out;

    embed_kernel<<<(S*DM + 255)/256, 256>>>(tokens, W_E, W_pos, p_resid);

    for (int l = 0; l < L; l++) {
        const float* wq = W_Q + (size_t)l*H*DM*DH;
        const float* wk = W_K + (size_t)l*H*DM*DH;
        const float* wv = W_V + (size_t)l*H*DM*DH;
        const float* wo = W_O + (size_t)l*H*DH*DM;
        const float* bq = b_Q + (size_t)l*H*DH;
        const float* bk = b_K + (size_t)l*H*DH;
        const float* bv = b_V + (size_t)l*H*DH;
        const float* bo = b_O + (size_t)l*DM;
        const float* l1w = ln1_w + (size_t)l*DM, *l1b = ln1_b + (size_t)l*DM;
        const float* l2w = ln2_w + (size_t)l*DM, *l2b = ln2_b + (size_t)l*DM;
        const float* wi = W_in  + (size_t)l*DM*DMLP;
        const float* bi = b_in  + (size_t)l*DMLP;
        const float* wu2= W_out + (size_t)l*DMLP*DM;
        const float* bo2= b_out + (size_t)l*DM;

        pack_qkv_kernel<<<(DM*DM + 255)/256, 256>>>(wq, wk, wv, bq, bk, bv);

        ln_kernel<<<S, 256>>>(p_resid, l1w, l1b, p_x);

        mma_gemm_kernel<0><<<dim3(QKVN/BN, S/BM), 256>>>(
            p_x, p_wqkv, p_bqkv, nullptr, p_qkv, S, QKVN, DM);

        attn_flash_kernel<<<dim3(S/128, H), 128>>>(p_qkv, p_z);

        mma_gemm_kernel<0><<<dim3(DM/BN, S/BM), 256>>>(
            p_z, wo, bo, p_resid, p_resid, S, DM, DM);

        ln_kernel<<<S, 256>>>(p_resid, l2w, l2b, p_x);

        mma_gemm_kernel<1><<<dim3(DMLP/BN, S/BM), 256>>>(
            p_x, wi, bi, nullptr, p_post, S, DMLP, DM);

        mma_gemm_kernel<0><<<dim3(DM/BN, S/BM), 256>>>(
            p_post, wu2, bo2, p_resid, p_resid, S, DM, DMLP);
    }

    ln_kernel<<<S, 256>>>(p_resid, lnf_w, lnf_b, p_x);
    mma_gemm_kernel<0><<<dim3((NV + BN - 1)/BN, S/BM), 256>>>(
        p_x, W_U, b_U, nullptr, out, S, NV, DM);

    const long long LOG_N  = (long long)S * NV;
    const long long RES_N  = (long long)S * DM;
    const long long POST_N = (long long)S * DMLP;
    long long osz = (long long)out_size;
    if (osz >= LOG_N + RES_N)
        copy_kernel<<<(int)((RES_N + 255)/256), 256>>>(p_resid, out + LOG_N, (int)RES_N);
    if (osz >= LOG_N + RES_N + POST_N)
        copy_kernel<<<(int)((POST_N + 255)/256), 256>>>(p_post, out + LOG_N + RES_N, (int)POST_N);
}

// round 6
// speedup vs baseline: 4.5886x; 1.1235x over previous
#include <cuda_runtime.h>
#include <cuda_bf16.h>
#include <math.h>
#include <stdint.h>

// ---------------- problem constants ----------------
#define S      2048
#define DM     1024
#define H      16
#define DH     64
#define DMLP   4096
#define NV     50257
#define NVP    50304      // NV padded to multiple of 64
#define L      2
#define QKVN   (3*DM)     // 3072
#define KH_DM  (DM/2)     // 512
#define KH_MLP (DMLP/2)   // 2048

// ---------------- static scratch ----------------
__device__ float g_resid[S*DM];
__device__ float g_qkv[S*QKVN];
__device__ float g_post[S*DMLP];
__device__ float g_bqkv[L*QKVN];

// packed activation planes (k-pair uint32: lo16 = bf16(k), hi16 = bf16(k+1))
__device__ uint32_t a_x_h[S*KH_DM],  a_x_l[S*KH_DM];
__device__ uint32_t a_z_h[S*KH_DM],  a_z_l[S*KH_DM];
__device__ uint32_t a_p_h[S*KH_MLP], a_p_l[S*KH_MLP];

// packed weight planes [K/2][N]
__device__ uint32_t wqkv_h[L*KH_DM*QKVN], wqkv_l[L*KH_DM*QKVN];
__device__ uint32_t wo_h  [L*KH_DM*DM],   wo_l  [L*KH_DM*DM];
__device__ uint32_t wi_h  [L*KH_DM*DMLP], wi_l  [L*KH_DM*DMLP];
__device__ uint32_t wu2_h [L*KH_MLP*DM],  wu2_l [L*KH_MLP*DM];
__device__ uint32_t wU_h  [KH_DM*NVP],    wU_l  [KH_DM*NVP];

// ---------------- helpers ----------------
__device__ __forceinline__ void split_pack(float x0, float x1,
                                           uint32_t& hi, uint32_t& lo) {
    __nv_bfloat16 h0 = __float2bfloat16_rn(x0);
    __nv_bfloat16 h1 = __float2bfloat16_rn(x1);
    float r0 = x0 - __bfloat162float(h0);
    float r1 = x1 - __bfloat162float(h1);
    __nv_bfloat16 l0 = __float2bfloat16_rn(r0);
    __nv_bfloat16 l1 = __float2bfloat16_rn(r1);
    __nv_bfloat162 hp = __halves2bfloat162(h0, h1);
    __nv_bfloat162 lp = __halves2bfloat162(l0, l1);
    hi = *reinterpret_cast<uint32_t*>(&hp);
    lo = *reinterpret_cast<uint32_t*>(&lp);
}

__device__ __forceinline__ void mma_bf16(float c[4],
                                         const uint32_t a[4],
                                         const uint32_t b[2]) {
    asm volatile(
        "mma.sync.aligned.m16n8k16.row.col.f32.bf16.bf16.f32 "
        "{%0,%1,%2,%3}, {%4,%5,%6,%7}, {%8,%9}, {%0,%1,%2,%3};\n"
        : "+f"(c[0]), "+f"(c[1]), "+f"(c[2]), "+f"(c[3])
        : "r"(a[0]), "r"(a[1]), "r"(a[2]), "r"(a[3]),
          "r"(b[0]), "r"(b[1]));
}

__device__ __forceinline__ uint32_t cvta_s(const void* p) {
    return (uint32_t)__cvta_generic_to_shared(p);
}
__device__ __forceinline__ void cpa16(uint32_t dst, const void* src) {
    asm volatile("cp.async.cg.shared.global [%0], [%1], 16;\n"
                 :: "r"(dst), "l"(src) : "memory");
}
#define CP_COMMIT() asm volatile("cp.async.commit_group;\n" ::: "memory")
#define CP_WAIT(n)  asm volatile("cp.async.wait_group %0;\n" :: "n"(n) : "memory")

// f32x2 packed helpers (attention)
__device__ __forceinline__ unsigned long long pk2(float lo, float hi) {
    unsigned long long r;
    asm("mov.b64 %0, {%1,%2};" : "=l"(r) : "f"(lo), "f"(hi));
    return r;
}
__device__ __forceinline__ void unpk2(unsigned long long v, float& lo, float& hi) {
    asm("mov.b64 {%0,%1}, %2;" : "=f"(lo), "=f"(hi) : "l"(v));
}
__device__ __forceinline__ unsigned long long fma2(unsigned long long a,
                                                   unsigned long long b,
                                                   unsigned long long c) {
    unsigned long long r;
    asm("fma.rn.f32x2 %0, %1, %2, %3;" : "=l"(r) : "l"(a), "l"(b), "l"(c));
    return r;
}
__device__ __forceinline__ unsigned long long mul2(unsigned long long a,
                                                   unsigned long long b) {
    unsigned long long r;
    asm("mul.rn.f32x2 %0, %1, %2;" : "=l"(r) : "l"(a), "l"(b));
    return r;
}

// ---------------- embed ----------------
__global__ void embed_kernel(const int* __restrict__ tok,
                             const float* __restrict__ WE,
                             const float* __restrict__ Wpos,
                             float* __restrict__ resid) {
    int i = blockIdx.x * 256 + threadIdx.x;
    if (i >= S*DM) return;
    int s = i >> 10;
    int d = i & (DM-1);
    resid[i] = WE[(size_t)tok[s]*DM + d] + Wpos[i];
}

// ---------------- weight conversion: float[K][N] -> planes [K/2][NP] ------
__global__ void convert_w_kernel(const float* __restrict__ W,
                                 uint32_t* __restrict__ Ph,
                                 uint32_t* __restrict__ Pl,
                                 int K, int N, int NP) {
    long long i = (long long)blockIdx.x * 256 + threadIdx.x;
    long long tot = (long long)(K >> 1) * NP;
    if (i >= tot) return;
    int n = (int)(i % NP);
    long long kp = i / NP;
    float v0 = 0.f, v1 = 0.f;
    if (n < N) {
        v0 = W[(size_t)(2*kp)*N + n];
        v1 = W[(size_t)(2*kp + 1)*N + n];
    }
    uint32_t h, l;
    split_pack(v0, v1, h, l);
    Ph[i] = h; Pl[i] = l;
}

// ---------------- pack QKV weights directly to planes --------------------
__global__ void pack_qkv_kernel(const float* __restrict__ WQ,
                                const float* __restrict__ WK,
                                const float* __restrict__ WV,
                                const float* __restrict__ bQ,
                                const float* __restrict__ bK,
                                const float* __restrict__ bV,
                                uint32_t* __restrict__ Wh,
                                uint32_t* __restrict__ Wl,
                                float* __restrict__ bqkv) {
    int idx = blockIdx.x * 256 + threadIdx.x;
    if (idx >= KH_DM*DM) return;
    int kp = idx >> 10;
    int c  = idx & (DM-1);
    int h = c >> 6, e = c & (DH-1);
    size_t s0 = ((size_t)h*DM + 2*kp)*DH + e;
    size_t s1 = ((size_t)h*DM + 2*kp + 1)*DH + e;
    uint32_t hh, ll;
    split_pack(WQ[s0], WQ[s1], hh, ll);
    Wh[(size_t)kp*QKVN + c] = hh;        Wl[(size_t)kp*QKVN + c] = ll;
    split_pack(WK[s0], WK[s1], hh, ll);
    Wh[(size_t)kp*QKVN + DM + c] = hh;   Wl[(size_t)kp*QKVN + DM + c] = ll;
    split_pack(WV[s0], WV[s1], hh, ll);
    Wh[(size_t)kp*QKVN + 2*DM + c] = hh; Wl[(size_t)kp*QKVN + 2*DM + c] = ll;
    if (idx < DM) {
        bqkv[idx]        = bQ[idx];
        bqkv[DM + idx]   = bK[idx];
        bqkv[2*DM + idx] = bV[idx];
    }
}

// ---------------- layernorm -> packed planes ----------------
__global__ void ln_pack_kernel(const float* __restrict__ x,
                               const float* __restrict__ w,
                               const float* __restrict__ b,
                               uint32_t* __restrict__ Ph,
                               uint32_t* __restrict__ Pl) {
    __shared__ float rs[256], rs2[256];
    int r = blockIdx.x, tid = threadIdx.x;
    const float* xr = x + (size_t)r*DM;
    float s = 0.f, s2 = 0.f;
    #pragma unroll
    for (int i = tid; i < DM; i += 256) { float v = xr[i]; s += v; s2 += v*v; }
    rs[tid] = s; rs2[tid] = s2; __syncthreads();
    for (int o = 128; o > 0; o >>= 1) {
        if (tid < o) { rs[tid] += rs[tid+o]; rs2[tid] += rs2[tid+o]; }
        __syncthreads();
    }
    float mu  = rs[0] * (1.f/DM);
    float var = rs2[0] * (1.f/DM) - mu*mu;
    float inv = rsqrtf(var + 1e-5f);
    for (int j = tid; j < KH_DM; j += 256) {
        float y0 = (xr[2*j]   - mu) * inv * w[2*j]   + b[2*j];
        float y1 = (xr[2*j+1] - mu) * inv * w[2*j+1] + b[2*j+1];
        uint32_t h, l;
        split_pack(y0, y1, h, l);
        Ph[(size_t)r*KH_DM + j] = h;
        Pl[(size_t)r*KH_DM + j] = l;
    }
}

// ---------------- bf16 GEMM: packed planes, cp.async double-buffer --------
// C[M,N] = act(Asplit @ Bsplit + bias) (+R). A planes [M][K/2], B planes [K/2][NB].
// 3-product: hi*hi + hi*lo + lo*hi. ACT: 1=exact GELU. PACK: also emit packed C.
template <int ACT, int PACK>
__global__ __launch_bounds__(256, 2)
void bf16_gemm_kernel(const uint32_t* __restrict__ Ah, const uint32_t* __restrict__ Al,
                      const uint32_t* __restrict__ Bh, const uint32_t* __restrict__ Bl,
                      const float* __restrict__ bias, const float* __restrict__ R,
                      float* __restrict__ C,
                      uint32_t* __restrict__ Ph, uint32_t* __restrict__ Pl,
                      int N, int NB, int K) {
    __shared__ uint32_t As[2][2][128][12];   // [buf][plane][m][kp] (kp 0..7, pad to 12)
    __shared__ uint32_t Bs[2][2][8][72];     // [buf][plane][kp][n] (pad 64->72)

    const int tid  = threadIdx.x;
    const int lane = tid & 31;
    const int wid  = tid >> 5;
    const int g    = lane >> 2;
    const int t4   = lane & 3;
    const int wm   = wid >> 1;
    const int wn   = wid & 1;
    const int row0 = blockIdx.y * 128;
    const int col0 = blockIdx.x * 64;
    const int KH   = K >> 1;
    const int NIT  = KH >> 3;

    // staging coords
    const int arow = tid >> 1;      // 0..127
    const int ahalf = tid & 1;      // which 16B chunk of the 8-kp row
    const int bpl  = tid >> 7;      // 0/1 plane
    const int bkp  = (tid & 127) >> 4;
    const int bq   = tid & 15;

    float acc[2][4][4];
    #pragma unroll
    for (int mt = 0; mt < 2; mt++)
        #pragma unroll
        for (int nt = 0; nt < 4; nt++)
            #pragma unroll
            for (int i = 0; i < 4; i++) acc[mt][nt][i] = 0.f;

    auto issue = [&](int kp0, int buf) {
        const uint32_t* sa0 = Ah + (size_t)(row0 + arow)*KH + kp0 + ahalf*4;
        const uint32_t* sa1 = Al + (size_t)(row0 + arow)*KH + kp0 + ahalf*4;
        cpa16(cvta_s(&As[buf][0][arow][ahalf*4]), sa0);
        cpa16(cvta_s(&As[buf][1][arow][ahalf*4]), sa1);
        const uint32_t* bp = (bpl ? Bl : Bh) + (size_t)(kp0 + bkp)*NB + col0 + bq*4;
        cpa16(cvta_s(&Bs[buf][bpl][bkp][bq*4]), bp);
    };

    issue(0, 0);
    CP_COMMIT();

    for (int it = 0; it < NIT; it++) {
        int cur = it & 1;
        if (it + 1 < NIT) {
            issue((it + 1) * 8, cur ^ 1);
            CP_COMMIT();
            CP_WAIT(1);
        } else {
            CP_WAIT(0);
        }
        __syncthreads();

        uint32_t ah[2][4], al[2][4];
        #pragma unroll
        for (int mt = 0; mt < 2; mt++) {
            int rb = wm*32 + mt*16;
            ah[mt][0] = As[cur][0][rb + g    ][t4    ];
            ah[mt][1] = As[cur][0][rb + g + 8][t4    ];
            ah[mt][2] = As[cur][0][rb + g    ][t4 + 4];
            ah[mt][3] = As[cur][0][rb + g + 8][t4 + 4];
            al[mt][0] = As[cur][1][rb + g    ][t4    ];
            al[mt][1] = As[cur][1][rb + g + 8][t4    ];
            al[mt][2] = As[cur][1][rb + g    ][t4 + 4];
            al[mt][3] = As[cur][1][rb + g + 8][t4 + 4];
        }
        uint32_t bh[4][2], bl[4][2];
        #pragma unroll
        for (int nt = 0; nt < 4; nt++) {
            int cb = wn*32 + nt*8 + g;
            bh[nt][0] = Bs[cur][0][t4    ][cb];
            bh[nt][1] = Bs[cur][0][t4 + 4][cb];
            bl[nt][0] = Bs[cur][1][t4    ][cb];
            bl[nt][1] = Bs[cur][1][t4 + 4][cb];
        }
        #pragma unroll
        for (int mt = 0; mt < 2; mt++)
            #pragma unroll
            for (int nt = 0; nt < 4; nt++) {
                mma_bf16(acc[mt][nt], ah[mt], bh[nt]);
                mma_bf16(acc[mt][nt], ah[mt], bl[nt]);
                mma_bf16(acc[mt][nt], al[mt], bh[nt]);
            }
        __syncthreads();
    }

    // ---- epilogue ----
    #pragma unroll
    for (int mt = 0; mt < 2; mt++) {
        #pragma unroll
        for (int nt = 0; nt < 4; nt++) {
            float vv[4];
            #pragma unroll
            for (int i = 0; i < 4; i++) {
                int col = col0 + wn*32 + nt*8 + 2*t4 + (i & 1);
                float v = acc[mt][nt][i];
                if (bias && col < N) v += bias[col];
                if (ACT == 1) v = 0.5f * v * (1.f + erff(v * 0.70710678118654752f));
                vv[i] = v;
            }
            #pragma unroll
            for (int i = 0; i < 4; i++) {
                int row = row0 + wm*32 + mt*16 + g + (i >> 1)*8;
                int col = col0 + wn*32 + nt*8 + 2*t4 + (i & 1);
                if (col >= N) continue;
                float v = vv[i];
                if (R) v += R[(size_t)row*N + col];
                C[(size_t)row*N + col] = v;
            }
            if (PACK) {
                int cp = (col0 >> 1) + wn*16 + nt*4 + t4;
                int NH = N >> 1;
                uint32_t h, l;
                int r0p = row0 + wm*32 + mt*16 + g;
                split_pack(vv[0], vv[1], h, l);
                Ph[(size_t)r0p*NH + cp] = h;  Pl[(size_t)r0p*NH + cp] = l;
                split_pack(vv[2], vv[3], h, l);
                Ph[(size_t)(r0p + 8)*NH + cp] = h;  Pl[(size_t)(r0p + 8)*NH + cp] = l;
            }
        }
    }
}

// ---------------- flash attention (packed-z output) ----------------
#define KT 64
__global__ __launch_bounds__(128)
void attn_flash_kernel(const float* __restrict__ qkv,
                       uint32_t* __restrict__ Zh,
                       uint32_t* __restrict__ Zl) {
    const int qt  = (gridDim.x - 1) - blockIdx.x;
    const int h   = blockIdx.y;
    const int tid = threadIdx.x;
    const int q   = qt*128 + tid;
    const int qmax = qt*128 + 127;

    __shared__ unsigned long long Ks[KT][33];
    __shared__ unsigned long long Vs[KT][33];

    unsigned long long qp[32];
    {
        const float4* qrow = reinterpret_cast<const float4*>(
            qkv + (size_t)q*QKVN + h*DH);
        #pragma unroll
        for (int i = 0; i < 16; i++) {
            float4 v = qrow[i];
            qp[2*i]   = pk2(v.x, v.y);
            qp[2*i+1] = pk2(v.z, v.w);
        }
    }
    unsigned long long accp[32];
    #pragma unroll
    for (int i = 0; i < 32; i++) accp[i] = 0ULL;
    float m = -1e30f, lsum = 0.f;

    const int row  = tid >> 1;
    const int half = tid & 1;

    for (int t0 = 0; t0 <= qmax; t0 += KT) {
        __syncthreads();
        {
            const float4* ksrc = reinterpret_cast<const float4*>(
                qkv + (size_t)(t0 + row)*QKVN + DM + h*DH + half*32);
            const float4* vsrc = reinterpret_cast<const float4*>(
                qkv + (size_t)(t0 + row)*QKVN + 2*DM + h*DH + half*32);
            #pragma unroll
            for (int j = 0; j < 8; j++) {
                float4 kv = ksrc[j];
                Ks[row][half*16 + 2*j]     = pk2(kv.x, kv.y);
                Ks[row][half*16 + 2*j + 1] = pk2(kv.z, kv.w);
                float4 vvv = vsrc[j];
                Vs[row][half*16 + 2*j]     = pk2(vvv.x, vvv.y);
                Vs[row][half*16 + 2*j + 1] = pk2(vvv.z, vvv.w);
            }
        }
        __syncthreads();

        int len = q + 1 - t0;
        if (len > KT) len = KT;
        for (int t = 0; t < len; t++) {
            const unsigned long long* kr = Ks[t];
            unsigned long long d0 = 0ULL, d1 = 0ULL, d2 = 0ULL, d3 = 0ULL;
            #pragma unroll
            for (int i = 0; i < 8; i++) {
                d0 = fma2(qp[4*i    ], kr[4*i    ], d0);
                d1 = fma2(qp[4*i + 1], kr[4*i + 1], d1);
                d2 = fma2(qp[4*i + 2], kr[4*i + 2], d2);
                d3 = fma2(qp[4*i + 3], kr[4*i + 3], d3);
            }
            float a0, a1, b0, b1, c0, c1, e0, e1;
            unpk2(d0, a0, a1); unpk2(d1, b0, b1);
            unpk2(d2, c0, c1); unpk2(d3, e0, e1);
            float sc = ((a0 + a1) + (b0 + b1)) + ((c0 + c1) + (e0 + e1));
            sc *= 0.125f;

            float p;
            if (sc > m) {
                float r = __expf(m - sc);
                unsigned long long r2 = pk2(r, r);
                #pragma unroll
                for (int i = 0; i < 32; i++) accp[i] = mul2(accp[i], r2);
                lsum *= r;
                m = sc;
                p = 1.f;
            } else {
                p = __expf(sc - m);
            }
            lsum += p;
            unsigned long long pp = pk2(p, p);
            const unsigned long long* vr = Vs[t];
            #pragma unroll
            for (int i = 0; i < 32; i++)
                accp[i] = fma2(pp, vr[i], accp[i]);
        }
    }

    float inv = 1.f / lsum;
    #pragma unroll
    for (int i = 0; i < 32; i++) {
        float x0, x1;
        unpk2(accp[i], x0, x1);
        uint32_t hh, ll;
        split_pack(x0 * inv, x1 * inv, hh, ll);
        Zh[(size_t)q*KH_DM + h*32 + i] = hh;
        Zl[(size_t)q*KH_DM + h*32 + i] = ll;
    }
}

// ---------------- plain copy ----------------
__global__ void copy_kernel(const float* __restrict__ src, float* __restrict__ dst, int n) {
    int i = blockIdx.x * 256 + threadIdx.x;
    if (i < n) dst[i] = src[i];
}

// ---------------- launcher ----------------
extern "C" void kernel_launch(void* const* d_in, const int* in_sizes, int n_in,
                              void* d_out, int out_size) {
    const int*   tokens = (const int*)  d_in[0];
    const float* W_E    = (const float*)d_in[1];
    const float* W_pos  = (const float*)d_in[2];
    const float* ln1_w  = (const float*)d_in[3];
    const float* ln1_b  = (const float*)d_in[4];
    const float* W_Q    = (const float*)d_in[5];
    const float* b_Q    = (const float*)d_in[6];
    const float* W_K    = (const float*)d_in[7];
    const float* b_K    = (const float*)d_in[8];
    const float* W_V    = (const float*)d_in[9];
    const float* b_V    = (const float*)d_in[10];
    const float* W_O    = (const float*)d_in[11];
    const float* b_O    = (const float*)d_in[12];
    const float* ln2_w  = (const float*)d_in[13];
    const float* ln2_b  = (const float*)d_in[14];
    const float* W_in   = (const float*)d_in[15];
    const float* b_in   = (const float*)d_in[16];
    const float* W_out  = (const float*)d_in[17];
    const float* b_out  = (const float*)d_in[18];
    const float* lnf_w  = (const float*)d_in[19];
    const float* lnf_b  = (const float*)d_in[20];
    const float* W_U    = (const float*)d_in[21];
    const float* b_U    = (const float*)d_in[22];

    float *p_resid, *p_qkv, *p_post, *p_bqkv;
    cudaGetSymbolAddress((void**)&p_resid, g_resid);
    cudaGetSymbolAddress((void**)&p_qkv,   g_qkv);
    cudaGetSymbolAddress((void**)&p_post,  g_post);
    cudaGetSymbolAddress((void**)&p_bqkv,  g_bqkv);

    uint32_t *pxh, *pxl, *pzh, *pzl, *pph, *ppl;
    cudaGetSymbolAddress((void**)&pxh, a_x_h); cudaGetSymbolAddress((void**)&pxl, a_x_l);
    cudaGetSymbolAddress((void**)&pzh, a_z_h); cudaGetSymbolAddress((void**)&pzl, a_z_l);
    cudaGetSymbolAddress((void**)&pph, a_p_h); cudaGetSymbolAddress((void**)&ppl, a_p_l);

    uint32_t *pwqh, *pwql, *pwoh, *pwol, *pwih, *pwil, *pw2h, *pw2l, *pwUh, *pwUl;
    cudaGetSymbolAddress((void**)&pwqh, wqkv_h); cudaGetSymbolAddress((void**)&pwql, wqkv_l);
    cudaGetSymbolAddress((void**)&pwoh, wo_h);   cudaGetSymbolAddress((void**)&pwol, wo_l);
    cudaGetSymbolAddress((void**)&pwih, wi_h);   cudaGetSymbolAddress((void**)&pwil, wi_l);
    cudaGetSymbolAddress((void**)&pw2h, wu2_h);  cudaGetSymbolAddress((void**)&pw2l, wu2_l);
    cudaGetSymbolAddress((void**)&pwUh, wU_h);   cudaGetSymbolAddress((void**)&pwUl, wU_l);

    float* out = (float*)d_out;

    embed_kernel<<<(S*DM + 255)/256, 256>>>(tokens, W_E, W_pos, p_resid);

    // ---- one-time weight conversions (per launch) ----
    for (int l = 0; l < L; l++) {
        pack_qkv_kernel<<<(KH_DM*DM + 255)/256, 256>>>(
            W_Q + (size_t)l*H*DM*DH, W_K + (size_t)l*H*DM*DH, W_V + (size_t)l*H*DM*DH,
            b_Q + (size_t)l*H*DH, b_K + (size_t)l*H*DH, b_V + (size_t)l*H*DH,
            pwqh + (size_t)l*KH_DM*QKVN, pwql + (size_t)l*KH_DM*QKVN,
            p_bqkv + (size_t)l*QKVN);
        long long t;
        t = (long long)KH_DM*DM;
        convert_w_kernel<<<(int)((t + 255)/256), 256>>>(
            W_O + (size_t)l*H*DH*DM,
            pwoh + (size_t)l*KH_DM*DM, pwol + (size_t)l*KH_DM*DM, DM, DM, DM);
        t = (long long)KH_DM*DMLP;
        convert_w_kernel<<<(int)((t + 255)/256), 256>>>(
            W_in + (size_t)l*DM*DMLP,
            pwih + (size_t)l*KH_DM*DMLP, pwil + (size_t)l*KH_DM*DMLP, DM, DMLP, DMLP);
        t = (long long)KH_MLP*DM;
        convert_w_kernel<<<(int)((t + 255)/256), 256>>>(
            W_out + (size_t)l*DMLP*DM,
            pw2h + (size_t)l*KH_MLP*DM, pw2l + (size_t)l*KH_MLP*DM, DMLP, DM, DM);
    }
    {
        long long t = (long long)KH_DM*NVP;
        convert_w_kernel<<<(int)((t + 255)/256), 256>>>(W_U, pwUh, pwUl, DM, NV, NVP);
    }

    for (int l = 0; l < L; l++) {
        const float* bo  = b_O   + (size_t)l*DM;
        const float* l1w = ln1_w + (size_t)l*DM, *l1b = ln1_b + (size_t)l*DM;
        const float* l2w = ln2_w + (size_t)l*DM, *l2b = ln2_b + (size_t)l*DM;
        const float* bi  = b_in  + (size_t)l*DMLP;
        const float* bo2 = b_out + (size_t)l*DM;

        ln_pack_kernel<<<S, 256>>>(p_resid, l1w, l1b, pxh, pxl);

        // qkv = x @ wqkv + bqkv
        bf16_gemm_kernel<0,0><<<dim3(QKVN/64, S/128), 256>>>(
            pxh, pxl, pwqh + (size_t)l*KH_DM*QKVN, pwql + (size_t)l*KH_DM*QKVN,
            p_bqkv + (size_t)l*QKVN, nullptr, p_qkv, nullptr, nullptr,
            QKVN, QKVN, DM);

        attn_flash_kernel<<<dim3(S/128, H), 128>>>(p_qkv, pzh, pzl);

        // resid += z @ W_O + b_O
        bf16_gemm_kernel<0,0><<<dim3(DM/64, S/128), 256>>>(
            pzh, pzl, pwoh + (size_t)l*KH_DM*DM, pwol + (size_t)l*KH_DM*DM,
            bo, p_resid, p_resid, nullptr, nullptr, DM, DM, DM);

        ln_pack_kernel<<<S, 256>>>(p_resid, l2w, l2b, pxh, pxl);

        // post = gelu(x @ W_in + b_in)  (float + packed planes)
        bf16_gemm_kernel<1,1><<<dim3(DMLP/64, S/128), 256>>>(
            pxh, pxl, pwih + (size_t)l*KH_DM*DMLP, pwil + (size_t)l*KH_DM*DMLP,
            bi, nullptr, p_post, pph, ppl, DMLP, DMLP, DM);

        // resid += post @ W_out + b_out
        bf16_gemm_kernel<0,0><<<dim3(DM/64, S/128), 256>>>(
            pph, ppl, pw2h + (size_t)l*KH_MLP*DM, pw2l + (size_t)l*KH_MLP*DM,
            bo2, p_resid, p_resid, nullptr, nullptr, DM, DM, DMLP);
    }

    ln_pack_kernel<<<S, 256>>>(p_resid, lnf_w, lnf_b, pxh, pxl);
    bf16_gemm_kernel<0,0><<<dim3(NVP/64, S/128), 256>>>(
        pxh, pxl, pwUh, pwUl, b_U, nullptr, out, nullptr, nullptr,
        NV, NVP, DM);

    const long long LOG_N  = (long long)S * NV;
    const long long RES_N  = (long long)S * DM;
    const long long POST_N = (long long)S * DMLP;
    long long osz = (long long)out_size;
    if (osz >= LOG_N + RES_N)
        copy_kernel<<<(int)((RES_N + 255)/256), 256>>>(p_resid, out + LOG_N, (int)RES_N);
    if (osz >= LOG_N + RES_N + POST_N)
        copy_kernel<<<(int)((POST_N + 255)/256), 256>>>(p_post, out + LOG_N + RES_N, (int)POST_N);
}